// round 2
// baseline (speedup 1.0000x reference)
#include <cuda_runtime.h>
#include <cstdint>

// ---------------------------------------------------------------------------
// WindowAttention fused kernel (one CTA per window), TF32 mma.sync
//   x:[4096,49,256]  qkv_w:[256,768]  proj_w:[256,256]  proj_b:[256]
//   bias_table:[169,8]  rel_idx:[49,49] int32   out:[4096,49,256] fp32
// ---------------------------------------------------------------------------

constexpr int NTOK = 49;
constexpr int DIMC = 256;
constexpr int NH   = 8;
constexpr int MP   = 64;   // padded token rows

// smem strides (floats). Chosen so every mma fragment LDS is conflict-free:
//   A-style pattern wants stride % 32 == 4 ; B-style wants stride % 32 == 8
constexpr int SX  = 260;   // x          (A operand)        %32==4
constexpr int SW1 = 104;   // qkv W chunk(B operand)        %32==8
constexpr int SWP = 264;   // proj W chunk(B operand)       %32==8
constexpr int SQ  = 36;    // q / O_h    (A operand)        %32==4
constexpr int SK  = 36;    // k          (B via row access) %32==4
constexpr int SV  = 40;    // v          (B operand)        %32==8
constexpr int SA  = 68;    // scores/probs (A operand)      %32==4

constexpr int OFF_X  = 0;
constexpr int OFF_W  = OFF_X  + MP * SX;        // 16640
constexpr int OFF_Q  = OFF_W  + 8448;           // max(64*104, 32*264)=8448
constexpr int OFF_K  = OFF_Q  + MP * SQ;
constexpr int OFF_V  = OFF_K  + MP * SK;
constexpr int OFF_A  = OFF_V  + MP * SV;
constexpr int OFF_BT = OFF_A  + MP * SA;        // bias_table 169*8
constexpr int OFF_PB = OFF_BT + 169 * NH;       // proj_b 256
constexpr int FLOATS = OFF_PB + 256;
constexpr int SMEM_BYTES = FLOATS * 4 + 2432;   // + rel_idx as uint8 (2401, padded)

__device__ __forceinline__ float tf32r(float x) {
    uint32_t u;
    asm("cvt.rna.tf32.f32 %0, %1;" : "=r"(u) : "f"(x));
    return __uint_as_float(u);
}

__device__ __forceinline__ void mma8(float c[4],
                                     uint32_t a0, uint32_t a1, uint32_t a2, uint32_t a3,
                                     uint32_t b0, uint32_t b1) {
    asm volatile(
        "mma.sync.aligned.m16n8k8.row.col.f32.tf32.tf32.f32 "
        "{%0,%1,%2,%3}, {%4,%5,%6,%7}, {%8,%9}, {%0,%1,%2,%3};"
        : "+f"(c[0]), "+f"(c[1]), "+f"(c[2]), "+f"(c[3])
        : "r"(a0), "r"(a1), "r"(a2), "r"(a3), "r"(b0), "r"(b1));
}

__global__ void __launch_bounds__(256, 1)
win_attn_kernel(const float* __restrict__ x,
                const float* __restrict__ qkv_w,
                const float* __restrict__ proj_w,
                const float* __restrict__ proj_b,
                const float* __restrict__ bias_table,
                const int*   __restrict__ rel_idx,
                float*       __restrict__ out) {
    extern __shared__ float sm[];
    float* s_x  = sm + OFF_X;
    float* s_w  = sm + OFF_W;
    float* s_q  = sm + OFF_Q;
    float* s_k  = sm + OFF_K;
    float* s_v  = sm + OFF_V;
    float* s_at = sm + OFF_A;
    float* s_bt = sm + OFF_BT;
    float* s_pb = sm + OFF_PB;
    unsigned char* s_ri = (unsigned char*)(sm + FLOATS);

    const int tid  = threadIdx.x;
    const int w    = tid >> 5;
    const int lane = tid & 31;
    const int g    = lane >> 2;   // mma group id (0..7)
    const int tg   = lane & 3;    // thread-in-group (0..3)
    const int b    = blockIdx.x;

    const int m   = (w & 3) * 16; // warp's M tile row base
    const int grp = w >> 2;       // warp half (0/1)

    // ---- init loads: x window -> s_x (tf32-rounded, rows 49..63 zero) ----
    {
        const float4* x4 = (const float4*)(x + (size_t)b * (NTOK * DIMC));
        #pragma unroll
        for (int i = 0; i < 16; i++) {
            int idx = tid + i * 256;          // 0..4095 == 64 rows * 64 float4
            int r = idx >> 6, c4 = idx & 63;
            float4 v = make_float4(0.f, 0.f, 0.f, 0.f);
            if (idx < 3136) v = x4[idx];      // 49*64
            float4 o;
            o.x = tf32r(v.x); o.y = tf32r(v.y); o.z = tf32r(v.z); o.w = tf32r(v.w);
            *(float4*)(s_x + r * SX + c4 * 4) = o;
        }
        for (int i = tid; i < 2401; i += 256) s_ri[i] = (unsigned char)rel_idx[i];
        for (int i = tid; i < 169 * NH; i += 256) s_bt[i] = bias_table[i];
        if (tid < 256) s_pb[tid] = proj_b[tid];
    }

    // persistent proj accumulators: warp covers rows m..m+15, cols grp*128..+127
    float facc[16][4];
    #pragma unroll
    for (int j = 0; j < 16; j++) {
        facc[j][0] = 0.f; facc[j][1] = 0.f; facc[j][2] = 0.f; facc[j][3] = 0.f;
    }

    for (int h = 0; h < NH; h++) {
        // ================= GEMM1: qkv_h[64,96] = x[64,256] @ W1_h =========
        float acc1[6][4];
        #pragma unroll
        for (int nt = 0; nt < 6; nt++) {
            acc1[nt][0] = 0.f; acc1[nt][1] = 0.f; acc1[nt][2] = 0.f; acc1[nt][3] = 0.f;
        }
        const int nb1 = grp * 48;
        for (int kc = 0; kc < 4; kc++) {
            __syncthreads();   // protect s_w (and s_q from prev head's proj)
            // stage W1 chunk [64 x 96] into s_w (tf32-rounded)
            #pragma unroll
            for (int i = 0; i < 6; i++) {
                int idx  = tid + i * 256;     // 0..1535 float4
                int r    = idx / 24;
                int c4   = idx - r * 24;
                int sect = c4 >> 3;           // 0=q 1=k 2=v
                int cc   = (c4 & 7) << 2;
                const float4 v = *(const float4*)(qkv_w +
                    (size_t)(kc * 64 + r) * 768 + sect * 256 + h * 32 + cc);
                float4 o;
                o.x = tf32r(v.x); o.y = tf32r(v.y); o.z = tf32r(v.z); o.w = tf32r(v.w);
                *(float4*)(s_w + r * SW1 + sect * 32 + cc) = o;
            }
            __syncthreads();
            #pragma unroll
            for (int kk = 0; kk < 8; kk++) {
                const int ks = kk * 8;
                const int ac = kc * 64 + ks;
                uint32_t a0 = __float_as_uint(s_x[(m + g)     * SX + ac + tg]);
                uint32_t a1 = __float_as_uint(s_x[(m + g + 8) * SX + ac + tg]);
                uint32_t a2 = __float_as_uint(s_x[(m + g)     * SX + ac + tg + 4]);
                uint32_t a3 = __float_as_uint(s_x[(m + g + 8) * SX + ac + tg + 4]);
                #pragma unroll
                for (int nt = 0; nt < 6; nt++) {
                    const int n = nb1 + nt * 8 + g;
                    uint32_t b0 = __float_as_uint(s_w[(ks + tg)     * SW1 + n]);
                    uint32_t b1 = __float_as_uint(s_w[(ks + tg + 4) * SW1 + n]);
                    mma8(acc1[nt], a0, a1, a2, a3, b0, b1);
                }
            }
        }
        // store q (scaled), k, v  (tf32-rounded)
        {
            const float scale = 0.17677669529663687f; // 1/sqrt(32)
            #pragma unroll
            for (int nt = 0; nt < 6; nt++) {
                int col  = nb1 + nt * 8 + 2 * tg;
                int sect = col >> 5;
                int cl   = col & 31;
                int r0 = m + g, r1 = m + g + 8;
                if (sect == 0) {
                    s_q[r0 * SQ + cl]     = tf32r(acc1[nt][0] * scale);
                    s_q[r0 * SQ + cl + 1] = tf32r(acc1[nt][1] * scale);
                    s_q[r1 * SQ + cl]     = tf32r(acc1[nt][2] * scale);
                    s_q[r1 * SQ + cl + 1] = tf32r(acc1[nt][3] * scale);
                } else if (sect == 1) {
                    s_k[r0 * SK + cl]     = tf32r(acc1[nt][0]);
                    s_k[r0 * SK + cl + 1] = tf32r(acc1[nt][1]);
                    s_k[r1 * SK + cl]     = tf32r(acc1[nt][2]);
                    s_k[r1 * SK + cl + 1] = tf32r(acc1[nt][3]);
                } else {
                    s_v[r0 * SV + cl]     = tf32r(acc1[nt][0]);
                    s_v[r0 * SV + cl + 1] = tf32r(acc1[nt][1]);
                    s_v[r1 * SV + cl]     = tf32r(acc1[nt][2]);
                    s_v[r1 * SV + cl + 1] = tf32r(acc1[nt][3]);
                }
            }
        }
        __syncthreads();

        // ================= scores: S[64,64] = q @ k^T ======================
        {
            float sacc[4][4];
            #pragma unroll
            for (int nt = 0; nt < 4; nt++) {
                sacc[nt][0] = 0.f; sacc[nt][1] = 0.f; sacc[nt][2] = 0.f; sacc[nt][3] = 0.f;
            }
            #pragma unroll
            for (int kk = 0; kk < 4; kk++) {
                const int ks = kk * 8;
                uint32_t a0 = __float_as_uint(s_q[(m + g)     * SQ + ks + tg]);
                uint32_t a1 = __float_as_uint(s_q[(m + g + 8) * SQ + ks + tg]);
                uint32_t a2 = __float_as_uint(s_q[(m + g)     * SQ + ks + tg + 4]);
                uint32_t a3 = __float_as_uint(s_q[(m + g + 8) * SQ + ks + tg + 4]);
                #pragma unroll
                for (int nt = 0; nt < 4; nt++) {
                    const int n = grp * 32 + nt * 8 + g;
                    uint32_t b0 = __float_as_uint(s_k[n * SK + ks + tg]);
                    uint32_t b1 = __float_as_uint(s_k[n * SK + ks + tg + 4]);
                    mma8(sacc[nt], a0, a1, a2, a3, b0, b1);
                }
            }
            #pragma unroll
            for (int nt = 0; nt < 4; nt++) {
                int n = grp * 32 + nt * 8 + 2 * tg;
                s_at[(m + g)     * SA + n]     = sacc[nt][0];
                s_at[(m + g)     * SA + n + 1] = sacc[nt][1];
                s_at[(m + g + 8) * SA + n]     = sacc[nt][2];
                s_at[(m + g + 8) * SA + n + 1] = sacc[nt][3];
            }
        }
        __syncthreads();

        // ============ softmax (+bias) rows; 4 threads per row =============
        {
            const int r = tid >> 2, q4 = tid & 3;
            float mx = -1e30f;
            for (int j = q4; j < 49; j += 4) {
                float bi = (r < 49) ? s_bt[(int)s_ri[r * 49 + j] * 8 + h] : 0.f;
                float v = s_at[r * SA + j] + bi;
                s_at[r * SA + j] = v;
                mx = fmaxf(mx, v);
            }
            mx = fmaxf(mx, __shfl_xor_sync(0xffffffffu, mx, 1, 4));
            mx = fmaxf(mx, __shfl_xor_sync(0xffffffffu, mx, 2, 4));
            float sum = 0.f;
            for (int j = q4; j < 49; j += 4) {
                float e = __expf(s_at[r * SA + j] - mx);
                s_at[r * SA + j] = e;
                sum += e;
            }
            sum += __shfl_xor_sync(0xffffffffu, sum, 1, 4);
            sum += __shfl_xor_sync(0xffffffffu, sum, 2, 4);
            float rinv = 1.0f / sum;
            for (int j = q4; j < 49; j += 4)
                s_at[r * SA + j] = tf32r(s_at[r * SA + j] * rinv);
            for (int j = 49 + q4; j < 64; j += 4)   // mask padded key columns
                s_at[r * SA + j] = 0.f;
        }
        // stage proj_w rows [h*32 .. h*32+31] into s_w (overlap with softmax)
        #pragma unroll
        for (int i = 0; i < 8; i++) {
            int idx = tid + i * 256;            // 0..2047 float4
            int r = idx >> 6, c4 = idx & 63;
            const float4 v = *(const float4*)(proj_w + (size_t)(h * 32 + r) * 256 + c4 * 4);
            float4 o;
            o.x = tf32r(v.x); o.y = tf32r(v.y); o.z = tf32r(v.z); o.w = tf32r(v.w);
            *(float4*)(s_w + r * SWP + c4 * 4) = o;
        }
        __syncthreads();

        // ================= O_h[64,32] = P @ v ==============================
        {
            float oacc[2][4];
            oacc[0][0]=0.f; oacc[0][1]=0.f; oacc[0][2]=0.f; oacc[0][3]=0.f;
            oacc[1][0]=0.f; oacc[1][1]=0.f; oacc[1][2]=0.f; oacc[1][3]=0.f;
            #pragma unroll
            for (int kk = 0; kk < 8; kk++) {
                const int ks = kk * 8;
                uint32_t a0 = __float_as_uint(s_at[(m + g)     * SA + ks + tg]);
                uint32_t a1 = __float_as_uint(s_at[(m + g + 8) * SA + ks + tg]);
                uint32_t a2 = __float_as_uint(s_at[(m + g)     * SA + ks + tg + 4]);
                uint32_t a3 = __float_as_uint(s_at[(m + g + 8) * SA + ks + tg + 4]);
                #pragma unroll
                for (int nt = 0; nt < 2; nt++) {
                    const int n = grp * 16 + nt * 8 + g;
                    uint32_t b0 = __float_as_uint(s_v[(ks + tg)     * SV + n]);
                    uint32_t b1 = __float_as_uint(s_v[(ks + tg + 4) * SV + n]);
                    mma8(oacc[nt], a0, a1, a2, a3, b0, b1);
                }
            }
            // O_h -> s_q (q is dead), tf32-rounded, as A for proj
            #pragma unroll
            for (int nt = 0; nt < 2; nt++) {
                int n = grp * 16 + nt * 8 + 2 * tg;
                s_q[(m + g)     * SQ + n]     = tf32r(oacc[nt][0]);
                s_q[(m + g)     * SQ + n + 1] = tf32r(oacc[nt][1]);
                s_q[(m + g + 8) * SQ + n]     = tf32r(oacc[nt][2]);
                s_q[(m + g + 8) * SQ + n + 1] = tf32r(oacc[nt][3]);
            }
        }
        __syncthreads();

        // ======== proj rank-32 update: facc += O_h[64,32] @ Wp_h[32,256] ===
        {
            const int ncb = grp * 128;
            #pragma unroll
            for (int kk = 0; kk < 4; kk++) {
                const int ks = kk * 8;
                uint32_t a0 = __float_as_uint(s_q[(m + g)     * SQ + ks + tg]);
                uint32_t a1 = __float_as_uint(s_q[(m + g + 8) * SQ + ks + tg]);
                uint32_t a2 = __float_as_uint(s_q[(m + g)     * SQ + ks + tg + 4]);
                uint32_t a3 = __float_as_uint(s_q[(m + g + 8) * SQ + ks + tg + 4]);
                #pragma unroll
                for (int j = 0; j < 16; j++) {
                    const int n = ncb + j * 8 + g;
                    uint32_t b0 = __float_as_uint(s_w[(ks + tg)     * SWP + n]);
                    uint32_t b1 = __float_as_uint(s_w[(ks + tg + 4) * SWP + n]);
                    mma8(facc[j], a0, a1, a2, a3, b0, b1);
                }
            }
        }
    } // heads

    // ================= epilogue: + proj_b, store rows < 49 =================
    {
        const int ncb = grp * 128;
        float* ob = out + (size_t)b * (NTOK * DIMC);
        const int r0 = m + g, r1 = m + g + 8;
        #pragma unroll
        for (int j = 0; j < 16; j++) {
            const int c = ncb + j * 8 + 2 * tg;
            if (r0 < 49) {
                float2 v; v.x = facc[j][0] + s_pb[c]; v.y = facc[j][1] + s_pb[c + 1];
                *(float2*)(ob + r0 * 256 + c) = v;
            }
            if (r1 < 49) {
                float2 v; v.x = facc[j][2] + s_pb[c]; v.y = facc[j][3] + s_pb[c + 1];
                *(float2*)(ob + r1 * 256 + c) = v;
            }
        }
    }
}

extern "C" void kernel_launch(void* const* d_in, const int* in_sizes, int n_in,
                              void* d_out, int out_size) {
    (void)in_sizes; (void)n_in; (void)out_size;
    const float* x      = (const float*)d_in[0];
    const float* qkv_w  = (const float*)d_in[1];
    const float* proj_w = (const float*)d_in[2];
    const float* proj_b = (const float*)d_in[3];
    const float* bt     = (const float*)d_in[4];
    const int*   ri     = (const int*)d_in[5];
    float* out = (float*)d_out;

    cudaFuncSetAttribute(win_attn_kernel,
                         cudaFuncAttributeMaxDynamicSharedMemorySize, SMEM_BYTES);
    win_attn_kernel<<<4096, 256, SMEM_BYTES>>>(x, qkv_w, proj_w, proj_b, bt, ri, out);
}

// round 6
// speedup vs baseline: 1.0766x; 1.0766x over previous
#include <cuda_runtime.h>
#include <cstdint>

// ---------------------------------------------------------------------------
// WindowAttention fused (1 CTA = 1 window), TF32 mma.sync, head-pair fused,
// 32x48 register tiles (B-fragment reuse across 2 M-tiles).
// Softmax is branch-free (no divergent shfl) — fixes the r4/r5 deadlock.
// ---------------------------------------------------------------------------

constexpr int NTOK = 49;
constexpr int DIMC = 256;

// smem strides (floats): A-operand reads want stride%32==4, B-operand %32==8
constexpr int SX  = 260;   // x resident            (A)   %32==4
constexpr int SW1 = 200;   // qkv W chunk [32x192]  (B)   %32==8
constexpr int SWP = 264;   // proj W half [32x256]  (B)   %32==8
constexpr int SQ  = 68;    // q / O pair [64x64]    (A)   %32==4
constexpr int SK  = 68;    // k pair     [64x64]    (B-by-row) %32==4
constexpr int SV  = 72;    // v pair     [64x64]    (B)   %32==8
constexpr int SA  = 68;    // scores pair 2x[64x64] (A)   %32==4

constexpr int OFF_X  = 0;
constexpr int OFF_W  = OFF_X + 64 * SX;          // union: 32*200=6400 | 32*264=8448
constexpr int OFF_Q  = OFF_W + 8448;
constexpr int OFF_K  = OFF_Q + 64 * SQ;
constexpr int OFF_V  = OFF_K + 64 * SK;
constexpr int OFF_A  = OFF_V + 64 * SV;
constexpr int OFF_BT = OFF_A + 2 * 64 * SA;
constexpr int OFF_PB = OFF_BT + 1352;
constexpr int FLOATS = OFF_PB + 256;
constexpr int SMEM_BYTES = FLOATS * 4 + 2432;    // + rel_idx u8

__device__ __forceinline__ float tf32r(float x) {
    uint32_t u;
    asm("cvt.rna.tf32.f32 %0, %1;" : "=r"(u) : "f"(x));
    return __uint_as_float(u);
}

__device__ __forceinline__ void mma8(float c[4],
                                     float a0, float a1, float a2, float a3,
                                     float b0, float b1) {
    asm volatile(
        "mma.sync.aligned.m16n8k8.row.col.f32.tf32.tf32.f32 "
        "{%0,%1,%2,%3}, {%4,%5,%6,%7}, {%8,%9}, {%0,%1,%2,%3};"
        : "+f"(c[0]), "+f"(c[1]), "+f"(c[2]), "+f"(c[3])
        : "r"(__float_as_uint(a0)), "r"(__float_as_uint(a1)),
          "r"(__float_as_uint(a2)), "r"(__float_as_uint(a3)),
          "r"(__float_as_uint(b0)), "r"(__float_as_uint(b1)));
}

__global__ void __launch_bounds__(256, 1)
win_attn_kernel(const float* __restrict__ x,
                const float* __restrict__ qkv_w,
                const float* __restrict__ proj_w,
                const float* __restrict__ proj_b,
                const float* __restrict__ bias_table,
                const int*   __restrict__ rel_idx,
                float*       __restrict__ out) {
    extern __shared__ float sm[];
    float* s_x  = sm + OFF_X;
    float* s_w  = sm + OFF_W;
    float* s_q  = sm + OFF_Q;
    float* s_k  = sm + OFF_K;
    float* s_v  = sm + OFF_V;
    float* s_at = sm + OFF_A;
    float* s_bt = sm + OFF_BT;
    float* s_pb = sm + OFF_PB;
    unsigned char* s_ri = (unsigned char*)(sm + FLOATS);

    const int tid  = threadIdx.x;
    const int w    = tid >> 5;
    const int lane = tid & 31;
    const int g    = lane >> 2;
    const int tg   = lane & 3;
    const int b    = blockIdx.x;

    const int mi = w & 1;     // 32-row block (GEMM1/proj)
    const int nb = w >> 1;    // 0..3 N block
    // attention mapping (4 warps per head-of-pair)
    const int ahh = w >> 2;         // head within pair
    const int ami = (w & 3) & 1;    // 32-row block
    const int ani = (w & 3) >> 1;   // col block

    // ---- init staging: x window (rows>=49 zero), tables ----
    {
        const float4* x4 = (const float4*)(x + (size_t)b * (NTOK * DIMC));
        #pragma unroll
        for (int i = 0; i < 16; i++) {
            int idx = tid + i * 256;          // 0..4095 = 64 rows * 64 float4
            int r = idx >> 6, c4 = idx & 63;
            float4 v = make_float4(0.f, 0.f, 0.f, 0.f);
            if (idx < 3136) v = x4[idx];
            float4 o;
            o.x = tf32r(v.x); o.y = tf32r(v.y); o.z = tf32r(v.z); o.w = tf32r(v.w);
            *(float4*)(s_x + r * SX + c4 * 4) = o;
        }
        for (int i = tid; i < 2401; i += 256) s_ri[i] = (unsigned char)rel_idx[i];
        for (int i = tid; i < 1352; i += 256) s_bt[i] = bias_table[i];
        if (tid < 256) s_pb[tid] = proj_b[tid];
    }
    __syncthreads();

    // persistent proj accumulators: rows mi*32..+31, cols nb*64..+63
    float facc[2][8][4];
    #pragma unroll
    for (int mt = 0; mt < 2; mt++)
        #pragma unroll
        for (int j = 0; j < 8; j++) {
            facc[mt][j][0] = 0.f; facc[mt][j][1] = 0.f;
            facc[mt][j][2] = 0.f; facc[mt][j][3] = 0.f;
        }

    const float scale = 0.17677669529663687f;  // 1/sqrt(32)
    const float4* qw4 = (const float4*)qkv_w;
    const float4* pw4 = (const float4*)proj_w;

    for (int hp = 0; hp < 4; hp++) {
        const int h0 = 2 * hp;

        // ============ GEMM1: qkv_pair[64,192] = x[64,256] @ W1 ============
        float acc1[2][6][4];
        #pragma unroll
        for (int mt = 0; mt < 2; mt++)
            #pragma unroll
            for (int nt = 0; nt < 6; nt++) {
                acc1[mt][nt][0] = 0.f; acc1[mt][nt][1] = 0.f;
                acc1[mt][nt][2] = 0.f; acc1[mt][nt][3] = 0.f;
            }
        for (int kc = 0; kc < 8; kc++) {
            __syncthreads();   // prior readers of s_w done
            // stage W1 chunk [32 rows x 192 cols] for heads h0,h0+1
            #pragma unroll
            for (int i = 0; i < 6; i++) {
                int idx = tid + i * 256;        // 0..1535
                int r = idx / 48, c4 = idx % 48;
                int s = c4 >> 4, hh = (c4 >> 3) & 1, q4 = c4 & 7;
                float4 v = qw4[(size_t)(kc * 32 + r) * 192 + s * 64 + (h0 + hh) * 8 + q4];
                float4 o;
                o.x = tf32r(v.x); o.y = tf32r(v.y); o.z = tf32r(v.z); o.w = tf32r(v.w);
                *(float4*)(s_w + r * SW1 + 4 * c4) = o;
            }
            __syncthreads();
            #pragma unroll
            for (int kk = 0; kk < 4; kk++) {
                const int ks = kk * 8;
                const int ka = kc * 32 + ks;
                float a[2][4];
                #pragma unroll
                for (int mt = 0; mt < 2; mt++) {
                    const int r0 = mi * 32 + mt * 16 + g;
                    a[mt][0] = s_x[r0 * SX + ka + tg];
                    a[mt][1] = s_x[(r0 + 8) * SX + ka + tg];
                    a[mt][2] = s_x[r0 * SX + ka + tg + 4];
                    a[mt][3] = s_x[(r0 + 8) * SX + ka + tg + 4];
                }
                #pragma unroll
                for (int nt = 0; nt < 6; nt++) {
                    const int n = nb * 48 + nt * 8 + g;
                    float b0 = s_w[(ks + tg) * SW1 + n];
                    float b1 = s_w[(ks + tg + 4) * SW1 + n];
                    mma8(acc1[0][nt], a[0][0], a[0][1], a[0][2], a[0][3], b0, b1);
                    mma8(acc1[1][nt], a[1][0], a[1][1], a[1][2], a[1][3], b0, b1);
                }
            }
        }
        // scatter q (scaled) / k / v
        #pragma unroll
        for (int mt = 0; mt < 2; mt++) {
            const int r0 = mi * 32 + mt * 16 + g, r1 = r0 + 8;
            #pragma unroll
            for (int nt = 0; nt < 6; nt++) {
                const int colb = nb * 48 + nt * 8;
                const int s  = colb >> 6;
                const int hh = (colb >> 5) & 1;
                const int cl = (colb & 31) + 2 * tg;
                const int c = hh * 32 + cl;
                if (s == 0) {
                    s_q[r0 * SQ + c]     = tf32r(acc1[mt][nt][0] * scale);
                    s_q[r0 * SQ + c + 1] = tf32r(acc1[mt][nt][1] * scale);
                    s_q[r1 * SQ + c]     = tf32r(acc1[mt][nt][2] * scale);
                    s_q[r1 * SQ + c + 1] = tf32r(acc1[mt][nt][3] * scale);
                } else if (s == 1) {
                    s_k[r0 * SK + c]     = tf32r(acc1[mt][nt][0]);
                    s_k[r0 * SK + c + 1] = tf32r(acc1[mt][nt][1]);
                    s_k[r1 * SK + c]     = tf32r(acc1[mt][nt][2]);
                    s_k[r1 * SK + c + 1] = tf32r(acc1[mt][nt][3]);
                } else {
                    s_v[r0 * SV + c]     = tf32r(acc1[mt][nt][0]);
                    s_v[r0 * SV + c + 1] = tf32r(acc1[mt][nt][1]);
                    s_v[r1 * SV + c]     = tf32r(acc1[mt][nt][2]);
                    s_v[r1 * SV + c + 1] = tf32r(acc1[mt][nt][3]);
                }
            }
        }
        __syncthreads();

        // ============ scores: S_hh[64,64] = q_hh @ k_hh^T ==================
        {
            float sacc[2][4][4];
            #pragma unroll
            for (int mt = 0; mt < 2; mt++)
                #pragma unroll
                for (int nt = 0; nt < 4; nt++) {
                    sacc[mt][nt][0] = 0.f; sacc[mt][nt][1] = 0.f;
                    sacc[mt][nt][2] = 0.f; sacc[mt][nt][3] = 0.f;
                }
            const int hb = ahh * 32;
            #pragma unroll
            for (int kk = 0; kk < 4; kk++) {
                const int ks = kk * 8;
                float a[2][4];
                #pragma unroll
                for (int mt = 0; mt < 2; mt++) {
                    const int r0 = ami * 32 + mt * 16 + g;
                    a[mt][0] = s_q[r0 * SQ + hb + ks + tg];
                    a[mt][1] = s_q[(r0 + 8) * SQ + hb + ks + tg];
                    a[mt][2] = s_q[r0 * SQ + hb + ks + tg + 4];
                    a[mt][3] = s_q[(r0 + 8) * SQ + hb + ks + tg + 4];
                }
                #pragma unroll
                for (int nt = 0; nt < 4; nt++) {
                    const int n = ani * 32 + nt * 8 + g;
                    float b0 = s_k[n * SK + hb + ks + tg];
                    float b1 = s_k[n * SK + hb + ks + tg + 4];
                    mma8(sacc[0][nt], a[0][0], a[0][1], a[0][2], a[0][3], b0, b1);
                    mma8(sacc[1][nt], a[1][0], a[1][1], a[1][2], a[1][3], b0, b1);
                }
            }
            float* ab = s_at + ahh * (64 * SA);
            #pragma unroll
            for (int mt = 0; mt < 2; mt++) {
                const int r0 = ami * 32 + mt * 16 + g, r1 = r0 + 8;
                #pragma unroll
                for (int nt = 0; nt < 4; nt++) {
                    const int n = ani * 32 + nt * 8 + 2 * tg;
                    ab[r0 * SA + n]     = sacc[mt][nt][0];
                    ab[r0 * SA + n + 1] = sacc[mt][nt][1];
                    ab[r1 * SA + n]     = sacc[mt][nt][2];
                    ab[r1 * SA + n + 1] = sacc[mt][nt][3];
                }
            }
        }
        __syncthreads();

        // ====== softmax (+bias), 2 threads/row, 128 rows — BRANCH-FREE =====
        // All 256 threads execute both shuffles (no divergent participation).
        // Rows rl>=49 compute finite garbage that is never consumed.
        {
            const int r2 = tid >> 1, t2 = tid & 1;
            const int hh = r2 >> 6, rl = r2 & 63;
            const int rs = (rl < NTOK) ? rl : (NTOK - 1);   // clamped bias row
            float* ar = s_at + hh * (64 * SA) + rl * SA;
            const int head = h0 + hh;
            const unsigned char* rr = s_ri + rs * 49;
            float mx = -1e30f;
            for (int j = t2; j < 49; j += 2) {
                float v = ar[j] + s_bt[(int)rr[j] * 8 + head];
                ar[j] = v;
                mx = fmaxf(mx, v);
            }
            mx = fmaxf(mx, __shfl_xor_sync(0xffffffffu, mx, 1, 2));
            float sum = 0.f;
            for (int j = t2; j < 49; j += 2) {
                float e = __expf(ar[j] - mx);
                ar[j] = e; sum += e;
            }
            sum += __shfl_xor_sync(0xffffffffu, sum, 1, 2);
            float rinv = 1.0f / sum;
            for (int j = t2; j < 49; j += 2) ar[j] = tf32r(ar[j] * rinv);
            for (int j = 49 + t2; j < 64; j += 2) ar[j] = 0.f;
        }
        __syncthreads();

        // ============ O_hh[64,32] = P_hh @ v_hh ============================
        {
            float oacc[2][2][4];
            #pragma unroll
            for (int mt = 0; mt < 2; mt++)
                #pragma unroll
                for (int nt = 0; nt < 2; nt++) {
                    oacc[mt][nt][0] = 0.f; oacc[mt][nt][1] = 0.f;
                    oacc[mt][nt][2] = 0.f; oacc[mt][nt][3] = 0.f;
                }
            const float* ab = s_at + ahh * (64 * SA);
            const int hb = ahh * 32;
            #pragma unroll
            for (int kk = 0; kk < 8; kk++) {
                const int ks = kk * 8;
                float a[2][4];
                #pragma unroll
                for (int mt = 0; mt < 2; mt++) {
                    const int r0 = ami * 32 + mt * 16 + g;
                    a[mt][0] = ab[r0 * SA + ks + tg];
                    a[mt][1] = ab[(r0 + 8) * SA + ks + tg];
                    a[mt][2] = ab[r0 * SA + ks + tg + 4];
                    a[mt][3] = ab[(r0 + 8) * SA + ks + tg + 4];
                }
                #pragma unroll
                for (int nt = 0; nt < 2; nt++) {
                    const int n = ani * 16 + nt * 8 + g;
                    float b0 = s_v[(ks + tg) * SV + hb + n];
                    float b1 = s_v[(ks + tg + 4) * SV + hb + n];
                    mma8(oacc[0][nt], a[0][0], a[0][1], a[0][2], a[0][3], b0, b1);
                    mma8(oacc[1][nt], a[1][0], a[1][1], a[1][2], a[1][3], b0, b1);
                }
            }
            // O -> s_q (q dead): pair-O cols = hh*32 + d
            #pragma unroll
            for (int mt = 0; mt < 2; mt++) {
                const int r0 = ami * 32 + mt * 16 + g, r1 = r0 + 8;
                #pragma unroll
                for (int nt = 0; nt < 2; nt++) {
                    const int c = hb + ani * 16 + nt * 8 + 2 * tg;
                    s_q[r0 * SQ + c]     = tf32r(oacc[mt][nt][0]);
                    s_q[r0 * SQ + c + 1] = tf32r(oacc[mt][nt][1]);
                    s_q[r1 * SQ + c]     = tf32r(oacc[mt][nt][2]);
                    s_q[r1 * SQ + c + 1] = tf32r(oacc[mt][nt][3]);
                }
            }
        }

        // ============ proj: facc += O_pair[64,64] @ Wp[64,256] =============
        for (int kc2 = 0; kc2 < 2; kc2++) {
            __syncthreads();   // O stores done / prior Wp readers done
            #pragma unroll
            for (int i = 0; i < 8; i++) {
                int idx = tid + i * 256;       // 0..2047
                int r = idx >> 6, c4 = idx & 63;
                float4 v = pw4[(size_t)((h0 + kc2) * 32 + r) * 64 + c4];
                float4 o;
                o.x = tf32r(v.x); o.y = tf32r(v.y); o.z = tf32r(v.z); o.w = tf32r(v.w);
                *(float4*)(s_w + r * SWP + 4 * c4) = o;
            }
            __syncthreads();
            #pragma unroll
            for (int kk = 0; kk < 4; kk++) {
                const int ks = kk * 8;
                float a[2][4];
                #pragma unroll
                for (int mt = 0; mt < 2; mt++) {
                    const int r0 = mi * 32 + mt * 16 + g;
                    a[mt][0] = s_q[r0 * SQ + kc2 * 32 + ks + tg];
                    a[mt][1] = s_q[(r0 + 8) * SQ + kc2 * 32 + ks + tg];
                    a[mt][2] = s_q[r0 * SQ + kc2 * 32 + ks + tg + 4];
                    a[mt][3] = s_q[(r0 + 8) * SQ + kc2 * 32 + ks + tg + 4];
                }
                #pragma unroll
                for (int nt = 0; nt < 8; nt++) {
                    const int n = nb * 64 + nt * 8 + g;
                    float b0 = s_w[(ks + tg) * SWP + n];
                    float b1 = s_w[(ks + tg + 4) * SWP + n];
                    mma8(facc[0][nt], a[0][0], a[0][1], a[0][2], a[0][3], b0, b1);
                    mma8(facc[1][nt], a[1][0], a[1][1], a[1][2], a[1][3], b0, b1);
                }
            }
        }
    } // head pairs

    // ============ epilogue: out = facc + proj_b (rows < 49) ================
    {
        float* ob = out + (size_t)b * (NTOK * DIMC);
        #pragma unroll
        for (int mt = 0; mt < 2; mt++) {
            const int r0 = mi * 32 + mt * 16 + g, r1 = r0 + 8;
            #pragma unroll
            for (int nt = 0; nt < 8; nt++) {
                const int c = nb * 64 + nt * 8 + 2 * tg;
                if (r0 < NTOK) {
                    float2 v;
                    v.x = facc[mt][nt][0] + s_pb[c];
                    v.y = facc[mt][nt][1] + s_pb[c + 1];
                    *(float2*)(ob + r0 * DIMC + c) = v;
                }
                if (r1 < NTOK) {
                    float2 v;
                    v.x = facc[mt][nt][2] + s_pb[c];
                    v.y = facc[mt][nt][3] + s_pb[c + 1];
                    *(float2*)(ob + r1 * DIMC + c) = v;
                }
            }
        }
    }
}

extern "C" void kernel_launch(void* const* d_in, const int* in_sizes, int n_in,
                              void* d_out, int out_size) {
    (void)in_sizes; (void)n_in; (void)out_size;
    const float* x      = (const float*)d_in[0];
    const float* qkv_w  = (const float*)d_in[1];
    const float* proj_w = (const float*)d_in[2];
    const float* proj_b = (const float*)d_in[3];
    const float* bt     = (const float*)d_in[4];
    const int*   ri     = (const int*)d_in[5];
    float* out = (float*)d_out;

    cudaFuncSetAttribute(win_attn_kernel,
                         cudaFuncAttributeMaxDynamicSharedMemorySize, SMEM_BYTES);
    win_attn_kernel<<<4096, 256, SMEM_BYTES>>>(x, qkv_w, proj_w, proj_b, bt, ri, out);
}

// round 7
// speedup vs baseline: 1.1773x; 1.0936x over previous
#include <cuda_runtime.h>
#include <cstdint>

// ---------------------------------------------------------------------------
// WindowAttention fused (1 CTA = 1 window), TF32 mma.sync.
// R7: register softmax, O-buffer + single end proj, double-buffered staging.
// ---------------------------------------------------------------------------

constexpr int NTOK = 49;
constexpr int DIMC = 256;

constexpr int SX  = 260;   // x   (A)  %32==4, 49 rows
constexpr int SO  = 260;   // O   (A)  %32==4, 49 rows
constexpr int SQ  = 68;    // q pair   (A)
constexpr int SK  = 68;    // k pair
constexpr int SV  = 72;    // v pair   (B) %32==8
constexpr int SP  = 68;    // P        (A)
constexpr int SW1 = 200;   // qkv W chunk [32x192] (B) %32==8
constexpr int SWP = 264;   // proj W chunk [16x256] (B) %32==8

constexpr int OFF_X  = 0;                    // 49*260 = 12740
constexpr int OFF_O  = OFF_X + 49 * SX;      // 12740
constexpr int OFF_Q  = OFF_O + 49 * SO;      // 25480
constexpr int OFF_K  = OFF_Q + 64 * SQ;      // 29832
constexpr int OFF_V  = OFF_K + 64 * SK;      // 34184
constexpr int OFF_U  = OFF_V + 64 * SV;      // 38792 ; union region:
//   W1 dbl: 2 x 32*200 = 12800 | P: 2 x 64*68 = 8704 | Wp dbl: 2 x 16*264 = 8448
constexpr int OFF_BT = OFF_U + 12800;        // 51592
constexpr int OFF_PB = OFF_BT + 1352;        // 52944
constexpr int FLOATS = OFF_PB + 256;         // 53200
constexpr int SMEM_BYTES = FLOATS * 4 + 2432;  // + rel_idx u8 -> 215232 B

__device__ __forceinline__ float tf32r(float x) {
    uint32_t u;
    asm("cvt.rna.tf32.f32 %0, %1;" : "=r"(u) : "f"(x));
    return __uint_as_float(u);
}

__device__ __forceinline__ void mma8(float c[4],
                                     float a0, float a1, float a2, float a3,
                                     float b0, float b1) {
    asm volatile(
        "mma.sync.aligned.m16n8k8.row.col.f32.tf32.tf32.f32 "
        "{%0,%1,%2,%3}, {%4,%5,%6,%7}, {%8,%9}, {%0,%1,%2,%3};"
        : "+f"(c[0]), "+f"(c[1]), "+f"(c[2]), "+f"(c[3])
        : "r"(__float_as_uint(a0)), "r"(__float_as_uint(a1)),
          "r"(__float_as_uint(a2)), "r"(__float_as_uint(a3)),
          "r"(__float_as_uint(b0)), "r"(__float_as_uint(b1)));
}

// W1 chunk prefetch: [32 rows x 192 cols] for head pair h0 (6 float4/thread)
__device__ __forceinline__ void ldw1(float4 pf[6], const float4* qw4,
                                     int h0, int kc, int tid) {
    #pragma unroll
    for (int i = 0; i < 6; i++) {
        int idx = tid + i * 256;
        int r = idx / 48, c4 = idx % 48;
        int s = c4 >> 4, hh = (c4 >> 3) & 1, q4 = c4 & 7;
        pf[i] = qw4[(size_t)(kc * 32 + r) * 192 + s * 64 + (h0 + hh) * 8 + q4];
    }
}
__device__ __forceinline__ void stw1(float* wb, const float4 pf[6], int tid) {
    #pragma unroll
    for (int i = 0; i < 6; i++) {
        int idx = tid + i * 256;
        int r = idx / 48, c4 = idx % 48;
        float4 o;
        o.x = tf32r(pf[i].x); o.y = tf32r(pf[i].y);
        o.z = tf32r(pf[i].z); o.w = tf32r(pf[i].w);
        *(float4*)(wb + r * SW1 + 4 * c4) = o;
    }
}
// Wp chunk prefetch: [16 rows x 256 cols] (4 float4/thread)
__device__ __forceinline__ void ldwp(float4 pf[4], const float4* pw4,
                                     int kc, int tid) {
    #pragma unroll
    for (int i = 0; i < 4; i++) {
        int idx = tid + i * 256;
        int r = idx >> 6, c4 = idx & 63;
        pf[i] = pw4[(size_t)(kc * 16 + r) * 64 + c4];
    }
}
__device__ __forceinline__ void stwp(float* wb, const float4 pf[4], int tid) {
    #pragma unroll
    for (int i = 0; i < 4; i++) {
        int idx = tid + i * 256;
        int r = idx >> 6, c4 = idx & 63;
        float4 o;
        o.x = tf32r(pf[i].x); o.y = tf32r(pf[i].y);
        o.z = tf32r(pf[i].z); o.w = tf32r(pf[i].w);
        *(float4*)(wb + r * SWP + 4 * c4) = o;
    }
}

__global__ void __launch_bounds__(256, 1)
win_attn_kernel(const float* __restrict__ x,
                const float* __restrict__ qkv_w,
                const float* __restrict__ proj_w,
                const float* __restrict__ proj_b,
                const float* __restrict__ bias_table,
                const int*   __restrict__ rel_idx,
                float*       __restrict__ out) {
    extern __shared__ float sm[];
    float* s_x  = sm + OFF_X;
    float* s_o  = sm + OFF_O;
    float* s_q  = sm + OFF_Q;
    float* s_k  = sm + OFF_K;
    float* s_v  = sm + OFF_V;
    float* s_u  = sm + OFF_U;   // W1 dbl | P | Wp dbl
    float* s_bt = sm + OFF_BT;
    float* s_pb = sm + OFF_PB;
    unsigned char* s_ri = (unsigned char*)(sm + FLOATS);

    const int tid  = threadIdx.x;
    const int w    = tid >> 5;
    const int lane = tid & 31;
    const int g    = lane >> 2;
    const int tg   = lane & 3;
    const int b    = blockIdx.x;

    const int mi = w & 1;      // GEMM1/proj: 32-row block
    const int nb = w >> 1;     // GEMM1/proj: N block
    const int ahh = w >> 2;    // attention: head within pair
    const int R   = (w & 3) * 16;  // attention: row base

    // ---- init staging: x (49 rows), tables ----
    {
        const float4* x4 = (const float4*)(x + (size_t)b * (NTOK * DIMC));
        #pragma unroll
        for (int i = 0; i < 13; i++) {
            int idx = tid + i * 256;
            if (idx < 3136) {
                int r = idx >> 6, c4 = idx & 63;
                float4 v = x4[idx];
                float4 o;
                o.x = tf32r(v.x); o.y = tf32r(v.y); o.z = tf32r(v.z); o.w = tf32r(v.w);
                *(float4*)(s_x + r * SX + c4 * 4) = o;
            }
        }
        for (int i = tid; i < 2401; i += 256) s_ri[i] = (unsigned char)rel_idx[i];
        for (int i = tid; i < 1352; i += 256) s_bt[i] = bias_table[i];
        if (tid < 256) s_pb[tid] = proj_b[tid];
    }
    __syncthreads();

    const float scale = 0.17677669529663687f;  // 1/sqrt(32)
    const float4* qw4 = (const float4*)qkv_w;
    const float4* pw4 = (const float4*)proj_w;

    for (int hp = 0; hp < 4; hp++) {
        const int h0 = 2 * hp;

        // ============ GEMM1: qkv_pair[64,192] = x @ W1 (dbl-buffered) ======
        float acc1[2][6][4];
        #pragma unroll
        for (int mt = 0; mt < 2; mt++)
            #pragma unroll
            for (int nt = 0; nt < 6; nt++) {
                acc1[mt][nt][0] = 0.f; acc1[mt][nt][1] = 0.f;
                acc1[mt][nt][2] = 0.f; acc1[mt][nt][3] = 0.f;
            }
        {
            float4 pf[6];
            ldw1(pf, qw4, h0, 0, tid);
            for (int kc = 0; kc < 8; kc++) {
                float* wb = s_u + (kc & 1) * 6400;
                stw1(wb, pf, tid);
                if (kc < 7) ldw1(pf, qw4, h0, kc + 1, tid);
                __syncthreads();
                #pragma unroll
                for (int kk = 0; kk < 4; kk++) {
                    const int ks = kk * 8;
                    const int ka = kc * 32 + ks;
                    float a[2][4];
                    #pragma unroll
                    for (int mt = 0; mt < 2; mt++) {
                        const int r0 = mi * 32 + mt * 16 + g;
                        const int rc0 = (r0 < 49) ? r0 : 48;
                        const int rc1 = (r0 + 8 < 49) ? r0 + 8 : 48;
                        a[mt][0] = s_x[rc0 * SX + ka + tg];
                        a[mt][1] = s_x[rc1 * SX + ka + tg];
                        a[mt][2] = s_x[rc0 * SX + ka + tg + 4];
                        a[mt][3] = s_x[rc1 * SX + ka + tg + 4];
                    }
                    #pragma unroll
                    for (int nt = 0; nt < 6; nt++) {
                        const int n = nb * 48 + nt * 8 + g;
                        float b0 = wb[(ks + tg) * SW1 + n];
                        float b1 = wb[(ks + tg + 4) * SW1 + n];
                        mma8(acc1[0][nt], a[0][0], a[0][1], a[0][2], a[0][3], b0, b1);
                        mma8(acc1[1][nt], a[1][0], a[1][1], a[1][2], a[1][3], b0, b1);
                    }
                }
            }
        }
        // scatter q (scaled) / k / v
        #pragma unroll
        for (int mt = 0; mt < 2; mt++) {
            const int r0 = mi * 32 + mt * 16 + g, r1 = r0 + 8;
            #pragma unroll
            for (int nt = 0; nt < 6; nt++) {
                const int colb = nb * 48 + nt * 8;
                const int s  = colb >> 6;
                const int hh = (colb >> 5) & 1;
                const int cl = (colb & 31) + 2 * tg;
                const int c = hh * 32 + cl;
                if (s == 0) {
                    s_q[r0 * SQ + c]     = tf32r(acc1[mt][nt][0] * scale);
                    s_q[r0 * SQ + c + 1] = tf32r(acc1[mt][nt][1] * scale);
                    s_q[r1 * SQ + c]     = tf32r(acc1[mt][nt][2] * scale);
                    s_q[r1 * SQ + c + 1] = tf32r(acc1[mt][nt][3] * scale);
                } else if (s == 1) {
                    s_k[r0 * SK + c]     = tf32r(acc1[mt][nt][0]);
                    s_k[r0 * SK + c + 1] = tf32r(acc1[mt][nt][1]);
                    s_k[r1 * SK + c]     = tf32r(acc1[mt][nt][2]);
                    s_k[r1 * SK + c + 1] = tf32r(acc1[mt][nt][3]);
                } else {
                    s_v[r0 * SV + c]     = tf32r(acc1[mt][nt][0]);
                    s_v[r0 * SV + c + 1] = tf32r(acc1[mt][nt][1]);
                    s_v[r1 * SV + c]     = tf32r(acc1[mt][nt][2]);
                    s_v[r1 * SV + c + 1] = tf32r(acc1[mt][nt][3]);
                }
            }
        }
        __syncthreads();

        // ============ scores (warp = 16 rows x 64 cols of one head) ========
        float sacc[8][4];
        #pragma unroll
        for (int nt = 0; nt < 8; nt++) {
            sacc[nt][0] = 0.f; sacc[nt][1] = 0.f;
            sacc[nt][2] = 0.f; sacc[nt][3] = 0.f;
        }
        {
            const int hb = ahh * 32;
            #pragma unroll
            for (int kk = 0; kk < 4; kk++) {
                const int ks = kk * 8;
                float a0 = s_q[(R + g)     * SQ + hb + ks + tg];
                float a1 = s_q[(R + 8 + g) * SQ + hb + ks + tg];
                float a2 = s_q[(R + g)     * SQ + hb + ks + tg + 4];
                float a3 = s_q[(R + 8 + g) * SQ + hb + ks + tg + 4];
                #pragma unroll
                for (int nt = 0; nt < 8; nt++) {
                    const int n = nt * 8 + g;
                    float b0 = s_k[n * SK + hb + ks + tg];
                    float b1 = s_k[n * SK + hb + ks + tg + 4];
                    mma8(sacc[nt], a0, a1, a2, a3, b0, b1);
                }
            }
        }

        // ============ softmax in registers (branch-free, quad shuffles) ====
        {
            const int head = h0 + ahh;
            const int row0 = R + g, row1 = R + 8 + g;
            const int rs0 = (row0 < 49) ? row0 : 48;
            const int rs1 = (row1 < 49) ? row1 : 48;
            const unsigned char* rr0 = s_ri + rs0 * 49;
            const unsigned char* rr1 = s_ri + rs1 * 49;
            float mx0 = -1e30f, mx1 = -1e30f;
            #pragma unroll
            for (int nt = 0; nt < 8; nt++) {
                const int c0 = nt * 8 + 2 * tg, c1 = c0 + 1;
                float v;
                v = (c0 < 49) ? sacc[nt][0] + s_bt[(int)rr0[c0 < 49 ? c0 : 0] * 8 + head] : -1e30f;
                sacc[nt][0] = v; mx0 = fmaxf(mx0, v);
                v = (c1 < 49) ? sacc[nt][1] + s_bt[(int)rr0[c1 < 49 ? c1 : 0] * 8 + head] : -1e30f;
                sacc[nt][1] = v; mx0 = fmaxf(mx0, v);
                v = (c0 < 49) ? sacc[nt][2] + s_bt[(int)rr1[c0 < 49 ? c0 : 0] * 8 + head] : -1e30f;
                sacc[nt][2] = v; mx1 = fmaxf(mx1, v);
                v = (c1 < 49) ? sacc[nt][3] + s_bt[(int)rr1[c1 < 49 ? c1 : 0] * 8 + head] : -1e30f;
                sacc[nt][3] = v; mx1 = fmaxf(mx1, v);
            }
            mx0 = fmaxf(mx0, __shfl_xor_sync(0xffffffffu, mx0, 1, 4));
            mx0 = fmaxf(mx0, __shfl_xor_sync(0xffffffffu, mx0, 2, 4));
            mx1 = fmaxf(mx1, __shfl_xor_sync(0xffffffffu, mx1, 1, 4));
            mx1 = fmaxf(mx1, __shfl_xor_sync(0xffffffffu, mx1, 2, 4));
            float sum0 = 0.f, sum1 = 0.f;
            #pragma unroll
            for (int nt = 0; nt < 8; nt++) {
                float e;
                e = __expf(sacc[nt][0] - mx0); sacc[nt][0] = e; sum0 += e;
                e = __expf(sacc[nt][1] - mx0); sacc[nt][1] = e; sum0 += e;
                e = __expf(sacc[nt][2] - mx1); sacc[nt][2] = e; sum1 += e;
                e = __expf(sacc[nt][3] - mx1); sacc[nt][3] = e; sum1 += e;
            }
            sum0 += __shfl_xor_sync(0xffffffffu, sum0, 1, 4);
            sum0 += __shfl_xor_sync(0xffffffffu, sum0, 2, 4);
            sum1 += __shfl_xor_sync(0xffffffffu, sum1, 1, 4);
            sum1 += __shfl_xor_sync(0xffffffffu, sum1, 2, 4);
            const float ri0 = 1.0f / sum0, ri1 = 1.0f / sum1;
            // write P (tf32) into union region
            float* pb_ = s_u + ahh * (64 * SP);
            #pragma unroll
            for (int nt = 0; nt < 8; nt++) {
                const int c = nt * 8 + 2 * tg;
                float2 v0, v1;
                v0.x = tf32r(sacc[nt][0] * ri0); v0.y = tf32r(sacc[nt][1] * ri0);
                v1.x = tf32r(sacc[nt][2] * ri1); v1.y = tf32r(sacc[nt][3] * ri1);
                *(float2*)(pb_ + row0 * SP + c) = v0;
                *(float2*)(pb_ + row1 * SP + c) = v1;
            }
        }
        __syncthreads();

        // ============ O_head[16..,32] = P @ v ; store to s_o ===============
        {
            float oacc[4][4];
            #pragma unroll
            for (int nt = 0; nt < 4; nt++) {
                oacc[nt][0] = 0.f; oacc[nt][1] = 0.f;
                oacc[nt][2] = 0.f; oacc[nt][3] = 0.f;
            }
            const float* pb_ = s_u + ahh * (64 * SP);
            const int hb = ahh * 32;
            #pragma unroll
            for (int kk = 0; kk < 8; kk++) {
                const int ks = kk * 8;
                float a0 = pb_[(R + g)     * SP + ks + tg];
                float a1 = pb_[(R + 8 + g) * SP + ks + tg];
                float a2 = pb_[(R + g)     * SP + ks + tg + 4];
                float a3 = pb_[(R + 8 + g) * SP + ks + tg + 4];
                #pragma unroll
                for (int nt = 0; nt < 4; nt++) {
                    const int n = nt * 8 + g;
                    float b0 = s_v[(ks + tg)     * SV + hb + n];
                    float b1 = s_v[(ks + tg + 4) * SV + hb + n];
                    mma8(oacc[nt], a0, a1, a2, a3, b0, b1);
                }
            }
            const int row0 = R + g, row1 = R + 8 + g;
            const int cb = (h0 + ahh) * 32;
            #pragma unroll
            for (int nt = 0; nt < 4; nt++) {
                const int c = cb + nt * 8 + 2 * tg;
                if (row0 < 49) {
                    float2 v; v.x = tf32r(oacc[nt][0]); v.y = tf32r(oacc[nt][1]);
                    *(float2*)(s_o + row0 * SO + c) = v;
                }
                if (row1 < 49) {
                    float2 v; v.x = tf32r(oacc[nt][2]); v.y = tf32r(oacc[nt][3]);
                    *(float2*)(s_o + row1 * SO + c) = v;
                }
            }
        }
        __syncthreads();   // P reads + O writes done before next pair reuses U
    } // head pairs

    // ============ proj: out = O[64,256] @ Wp[256,256] + b (dbl-buffered) ===
    {
        float facc[2][8][4];
        #pragma unroll
        for (int mt = 0; mt < 2; mt++)
            #pragma unroll
            for (int j = 0; j < 8; j++) {
                facc[mt][j][0] = 0.f; facc[mt][j][1] = 0.f;
                facc[mt][j][2] = 0.f; facc[mt][j][3] = 0.f;
            }
        float4 pf[4];
        ldwp(pf, pw4, 0, tid);
        for (int kc = 0; kc < 16; kc++) {
            float* wb = s_u + (kc & 1) * 4224;
            stwp(wb, pf, tid);
            if (kc < 15) ldwp(pf, pw4, kc + 1, tid);
            __syncthreads();
            #pragma unroll
            for (int kk = 0; kk < 2; kk++) {
                const int ks = kk * 8;
                const int ka = kc * 16 + ks;
                float a[2][4];
                #pragma unroll
                for (int mt = 0; mt < 2; mt++) {
                    const int r0 = mi * 32 + mt * 16 + g;
                    const int rc0 = (r0 < 49) ? r0 : 48;
                    const int rc1 = (r0 + 8 < 49) ? r0 + 8 : 48;
                    a[mt][0] = s_o[rc0 * SO + ka + tg];
                    a[mt][1] = s_o[rc1 * SO + ka + tg];
                    a[mt][2] = s_o[rc0 * SO + ka + tg + 4];
                    a[mt][3] = s_o[rc1 * SO + ka + tg + 4];
                }
                #pragma unroll
                for (int nt = 0; nt < 8; nt++) {
                    const int n = nb * 64 + nt * 8 + g;
                    float b0 = wb[(ks + tg) * SWP + n];
                    float b1 = wb[(ks + tg + 4) * SWP + n];
                    mma8(facc[0][nt], a[0][0], a[0][1], a[0][2], a[0][3], b0, b1);
                    mma8(facc[1][nt], a[1][0], a[1][1], a[1][2], a[1][3], b0, b1);
                }
            }
        }
        // epilogue
        float* ob = out + (size_t)b * (NTOK * DIMC);
        #pragma unroll
        for (int mt = 0; mt < 2; mt++) {
            const int r0 = mi * 32 + mt * 16 + g, r1 = r0 + 8;
            #pragma unroll
            for (int nt = 0; nt < 8; nt++) {
                const int c = nb * 64 + nt * 8 + 2 * tg;
                if (r0 < NTOK) {
                    float2 v;
                    v.x = facc[mt][nt][0] + s_pb[c];
                    v.y = facc[mt][nt][1] + s_pb[c + 1];
                    *(float2*)(ob + r0 * DIMC + c) = v;
                }
                if (r1 < NTOK) {
                    float2 v;
                    v.x = facc[mt][nt][2] + s_pb[c];
                    v.y = facc[mt][nt][3] + s_pb[c + 1];
                    *(float2*)(ob + r1 * DIMC + c) = v;
                }
            }
        }
    }
}

extern "C" void kernel_launch(void* const* d_in, const int* in_sizes, int n_in,
                              void* d_out, int out_size) {
    (void)in_sizes; (void)n_in; (void)out_size;
    const float* x      = (const float*)d_in[0];
    const float* qkv_w  = (const float*)d_in[1];
    const float* proj_w = (const float*)d_in[2];
    const float* proj_b = (const float*)d_in[3];
    const float* bt     = (const float*)d_in[4];
    const int*   ri     = (const int*)d_in[5];
    float* out = (float*)d_out;

    cudaFuncSetAttribute(win_attn_kernel,
                         cudaFuncAttributeMaxDynamicSharedMemorySize, SMEM_BYTES);
    win_attn_kernel<<<4096, 256, SMEM_BYTES>>>(x, qkv_w, proj_w, proj_b, bt, ri, out);
}

// round 8
// speedup vs baseline: 2.0802x; 1.7668x over previous
#include <cuda_runtime.h>
#include <cuda_fp16.h>
#include <cstdint>

// ---------------------------------------------------------------------------
// WindowAttention fused (1 CTA = 1 window), FP16 mma.sync m16n8k16 (f32 acc).
// R8: fp16 operands (same 10-bit mantissa as tf32), halved smem -> 2 CTAs/SM,
// weights pre-converted to half (transposed [n][k]) by a prologue kernel.
// ---------------------------------------------------------------------------

constexpr int NTOK = 49;
constexpr int DIMC = 256;

// strides in halves; all satisfy conflict-free fragment-load conditions
constexpr int HX  = 264;  // x   (A)
constexpr int HQ  = 72;   // q pair [64 x 64]
constexpr int HK  = 72;   // k pair [token][dim]
constexpr int HV  = 72;   // v^T  [dim][token]
constexpr int HP  = 72;   // P per head [64 x 64]
constexpr int HO  = 264;  // O   [49 x 256]
constexpr int HW1 = 40;   // W1^T chunk [192 n][32 k]
constexpr int HWP = 40;   // Wp^T chunk [256 n][32 k]

constexpr int OFF_X = 0;                  // 49*264 = 12936
constexpr int OFF_Q = 12944;
constexpr int OFF_K = OFF_Q + 64 * HQ;    // 17552
constexpr int OFF_V = OFF_K + 64 * HK;    // 22160
constexpr int OFF_O = OFF_V + 64 * HV;    // 26768 (+12936 = 39704)
constexpr int OFF_U = 39712;              // union: W1 7680 | P 9216 | Wp 10240
constexpr int HALVES = OFF_U + 10240;     // 49952
constexpr int SMEM_BYTES = HALVES * 2 + 5408 + 1024 + 2432;  // 108768

// half weights, transposed to [n][k] (k contiguous)
__device__ __half g_w1h[768 * 256];
__device__ __half g_wph[256 * 256];

__global__ void conv_w_kernel(const float* __restrict__ qkv_w,
                              const float* __restrict__ proj_w) {
    int t = blockIdx.x * blockDim.x + threadIdx.x;
    if (t < 768 * 32) {
        int n = t >> 5, kb = (t & 31) * 8;
        __half h[8];
        #pragma unroll
        for (int j = 0; j < 8; j++)
            h[j] = __float2half_rn(qkv_w[(size_t)(kb + j) * 768 + n]);
        *(uint4*)&g_w1h[n * 256 + kb] = *(uint4*)h;
    } else {
        int u = t - 768 * 32;
        int n = u >> 5, kb = (u & 31) * 8;
        __half h[8];
        #pragma unroll
        for (int j = 0; j < 8; j++)
            h[j] = __float2half_rn(proj_w[(size_t)(kb + j) * 256 + n]);
        *(uint4*)&g_wph[n * 256 + kb] = *(uint4*)h;
    }
}

__device__ __forceinline__ void mma16(float c[4],
                                      uint32_t a0, uint32_t a1, uint32_t a2, uint32_t a3,
                                      uint32_t b0, uint32_t b1) {
    asm volatile(
        "mma.sync.aligned.m16n8k16.row.col.f32.f16.f16.f32 "
        "{%0,%1,%2,%3}, {%4,%5,%6,%7}, {%8,%9}, {%0,%1,%2,%3};"
        : "+f"(c[0]), "+f"(c[1]), "+f"(c[2]), "+f"(c[3])
        : "r"(a0), "r"(a1), "r"(a2), "r"(a3), "r"(b0), "r"(b1));
}
__device__ __forceinline__ uint32_t ldh2(const __half* p) {
    return *(const uint32_t*)p;
}

__global__ void __launch_bounds__(256, 2)
win_attn_kernel(const float* __restrict__ x,
                const float* __restrict__ proj_b,
                const float* __restrict__ bias_table,
                const int*   __restrict__ rel_idx,
                float*       __restrict__ out) {
    extern __shared__ __half sh[];
    __half* s_x = sh + OFF_X;
    __half* s_q = sh + OFF_Q;
    __half* s_k = sh + OFF_K;
    __half* s_v = sh + OFF_V;
    __half* s_o = sh + OFF_O;
    __half* s_u = sh + OFF_U;
    float* s_bt = (float*)((char*)sh + HALVES * 2);
    float* s_pb = s_bt + 1352;
    unsigned char* s_ri = (unsigned char*)(s_pb + 256);

    const int tid  = threadIdx.x;
    const int w    = tid >> 5;
    const int lane = tid & 31;
    const int g    = lane >> 2;
    const int tg   = lane & 3;
    const int b    = blockIdx.x;

    const int mi = w & 1;          // GEMM1/proj 32-row block
    const int nb = w >> 1;         // GEMM1/proj N block
    const int ahh = w >> 2;        // attention: head within pair
    const int R   = (w & 3) * 16;  // attention: row base

    // ---- init: stage x (49 rows, f32 -> half), tables ----
    {
        const float4* x4 = (const float4*)(x + (size_t)b * (NTOK * DIMC));
        #pragma unroll
        for (int i = 0; i < 13; i++) {
            int idx = tid + i * 256;
            if (idx < 3136) {
                int r = idx >> 6, c4 = idx & 63;
                float4 v = x4[idx];
                __half2 h0 = __floats2half2_rn(v.x, v.y);
                __half2 h1 = __floats2half2_rn(v.z, v.w);
                __half2* dst = (__half2*)&s_x[r * HX + c4 * 4];
                dst[0] = h0; dst[1] = h1;
            }
        }
        for (int i = tid; i < 2401; i += 256) s_ri[i] = (unsigned char)rel_idx[i];
        for (int i = tid; i < 1352; i += 256) s_bt[i] = bias_table[i];
        if (tid < 256) s_pb[tid] = proj_b[tid];
    }
    __syncthreads();

    const float scale = 0.17677669529663687f;  // 1/sqrt(32)

    for (int hp = 0; hp < 4; hp++) {
        const int h0 = 2 * hp;

        // ======= GEMM1: qkv_pair[64,192] = x[64,256] @ W1, K-chunks of 32 ==
        float acc1[2][6][4];
        #pragma unroll
        for (int mt = 0; mt < 2; mt++)
            #pragma unroll
            for (int nt = 0; nt < 6; nt++) {
                acc1[mt][nt][0] = 0.f; acc1[mt][nt][1] = 0.f;
                acc1[mt][nt][2] = 0.f; acc1[mt][nt][3] = 0.f;
            }
        for (int kc = 0; kc < 8; kc++) {
            __syncthreads();   // prior readers of s_u done
            // stage W1^T chunk [192 n][32 k] from g_w1h
            #pragma unroll
            for (int i = 0; i < 3; i++) {
                int idx = tid + i * 256;          // 0..767
                int n = idx >> 2, c8 = idx & 3;
                int s = n >> 6, hh = (n >> 5) & 1, d = n & 31;
                int gn = s * 256 + (h0 + hh) * 32 + d;
                uint4 v = *(const uint4*)&g_w1h[gn * 256 + kc * 32 + c8 * 8];
                *(uint4*)&s_u[n * HW1 + c8 * 8] = v;
            }
            __syncthreads();
            #pragma unroll
            for (int kk = 0; kk < 2; kk++) {
                const int k0 = kc * 32 + kk * 16;   // x col
                const int kl = kk * 16;             // chunk col
                uint32_t a[2][4];
                #pragma unroll
                for (int mt = 0; mt < 2; mt++) {
                    const int r0 = mi * 32 + mt * 16 + g;
                    const int rc0 = (r0 < 49) ? r0 : 48;
                    const int rc1 = (r0 + 8 < 49) ? r0 + 8 : 48;
                    a[mt][0] = ldh2(&s_x[rc0 * HX + k0 + 2 * tg]);
                    a[mt][1] = ldh2(&s_x[rc1 * HX + k0 + 2 * tg]);
                    a[mt][2] = ldh2(&s_x[rc0 * HX + k0 + 2 * tg + 8]);
                    a[mt][3] = ldh2(&s_x[rc1 * HX + k0 + 2 * tg + 8]);
                }
                #pragma unroll
                for (int nt = 0; nt < 6; nt++) {
                    const int n = nb * 48 + nt * 8 + g;
                    uint32_t b0 = ldh2(&s_u[n * HW1 + kl + 2 * tg]);
                    uint32_t b1 = ldh2(&s_u[n * HW1 + kl + 2 * tg + 8]);
                    mma16(acc1[0][nt], a[0][0], a[0][1], a[0][2], a[0][3], b0, b1);
                    mma16(acc1[1][nt], a[1][0], a[1][1], a[1][2], a[1][3], b0, b1);
                }
            }
        }
        // scatter q (scaled) / k / v^T (half)
        #pragma unroll
        for (int mt = 0; mt < 2; mt++) {
            const int r0 = mi * 32 + mt * 16 + g, r1 = r0 + 8;
            #pragma unroll
            for (int nt = 0; nt < 6; nt++) {
                const int colb = nb * 48 + nt * 8;
                const int s = colb >> 6;
                const int cc = (colb & 63) + 2 * tg;
                if (s == 0) {
                    *(__half2*)&s_q[r0 * HQ + cc] =
                        __floats2half2_rn(acc1[mt][nt][0] * scale, acc1[mt][nt][1] * scale);
                    *(__half2*)&s_q[r1 * HQ + cc] =
                        __floats2half2_rn(acc1[mt][nt][2] * scale, acc1[mt][nt][3] * scale);
                } else if (s == 1) {
                    *(__half2*)&s_k[r0 * HK + cc] =
                        __floats2half2_rn(acc1[mt][nt][0], acc1[mt][nt][1]);
                    *(__half2*)&s_k[r1 * HK + cc] =
                        __floats2half2_rn(acc1[mt][nt][2], acc1[mt][nt][3]);
                } else {
                    s_v[cc * HV + r0]       = __float2half_rn(acc1[mt][nt][0]);
                    s_v[(cc + 1) * HV + r0] = __float2half_rn(acc1[mt][nt][1]);
                    s_v[cc * HV + r1]       = __float2half_rn(acc1[mt][nt][2]);
                    s_v[(cc + 1) * HV + r1] = __float2half_rn(acc1[mt][nt][3]);
                }
            }
        }
        __syncthreads();

        // ======= scores: warp = 16 rows x 64 cols of one head ==============
        float sacc[8][4];
        #pragma unroll
        for (int nt = 0; nt < 8; nt++) {
            sacc[nt][0] = 0.f; sacc[nt][1] = 0.f;
            sacc[nt][2] = 0.f; sacc[nt][3] = 0.f;
        }
        {
            #pragma unroll
            for (int kk = 0; kk < 2; kk++) {
                const int k0 = ahh * 32 + kk * 16;
                uint32_t a0 = ldh2(&s_q[(R + g) * HQ + k0 + 2 * tg]);
                uint32_t a1 = ldh2(&s_q[(R + 8 + g) * HQ + k0 + 2 * tg]);
                uint32_t a2 = ldh2(&s_q[(R + g) * HQ + k0 + 2 * tg + 8]);
                uint32_t a3 = ldh2(&s_q[(R + 8 + g) * HQ + k0 + 2 * tg + 8]);
                #pragma unroll
                for (int nt = 0; nt < 8; nt++) {
                    const int n = nt * 8 + g;
                    uint32_t b0 = ldh2(&s_k[n * HK + k0 + 2 * tg]);
                    uint32_t b1 = ldh2(&s_k[n * HK + k0 + 2 * tg + 8]);
                    mma16(sacc[nt], a0, a1, a2, a3, b0, b1);
                }
            }
        }

        // ======= softmax in registers (branch-free, quad shuffles) =========
        {
            const int head = h0 + ahh;
            const int row0 = R + g, row1 = R + 8 + g;
            const int rs0 = (row0 < 49) ? row0 : 48;
            const int rs1 = (row1 < 49) ? row1 : 48;
            const unsigned char* rr0 = s_ri + rs0 * 49;
            const unsigned char* rr1 = s_ri + rs1 * 49;
            float mx0 = -1e30f, mx1 = -1e30f;
            #pragma unroll
            for (int nt = 0; nt < 8; nt++) {
                const int c0 = nt * 8 + 2 * tg, c1 = c0 + 1;
                float v;
                v = (c0 < 49) ? sacc[nt][0] + s_bt[(int)rr0[c0 < 49 ? c0 : 0] * 8 + head] : -1e30f;
                sacc[nt][0] = v; mx0 = fmaxf(mx0, v);
                v = (c1 < 49) ? sacc[nt][1] + s_bt[(int)rr0[c1 < 49 ? c1 : 0] * 8 + head] : -1e30f;
                sacc[nt][1] = v; mx0 = fmaxf(mx0, v);
                v = (c0 < 49) ? sacc[nt][2] + s_bt[(int)rr1[c0 < 49 ? c0 : 0] * 8 + head] : -1e30f;
                sacc[nt][2] = v; mx1 = fmaxf(mx1, v);
                v = (c1 < 49) ? sacc[nt][3] + s_bt[(int)rr1[c1 < 49 ? c1 : 0] * 8 + head] : -1e30f;
                sacc[nt][3] = v; mx1 = fmaxf(mx1, v);
            }
            mx0 = fmaxf(mx0, __shfl_xor_sync(0xffffffffu, mx0, 1, 4));
            mx0 = fmaxf(mx0, __shfl_xor_sync(0xffffffffu, mx0, 2, 4));
            mx1 = fmaxf(mx1, __shfl_xor_sync(0xffffffffu, mx1, 1, 4));
            mx1 = fmaxf(mx1, __shfl_xor_sync(0xffffffffu, mx1, 2, 4));
            float sum0 = 0.f, sum1 = 0.f;
            #pragma unroll
            for (int nt = 0; nt < 8; nt++) {
                float e;
                e = __expf(sacc[nt][0] - mx0); sacc[nt][0] = e; sum0 += e;
                e = __expf(sacc[nt][1] - mx0); sacc[nt][1] = e; sum0 += e;
                e = __expf(sacc[nt][2] - mx1); sacc[nt][2] = e; sum1 += e;
                e = __expf(sacc[nt][3] - mx1); sacc[nt][3] = e; sum1 += e;
            }
            sum0 += __shfl_xor_sync(0xffffffffu, sum0, 1, 4);
            sum0 += __shfl_xor_sync(0xffffffffu, sum0, 2, 4);
            sum1 += __shfl_xor_sync(0xffffffffu, sum1, 1, 4);
            sum1 += __shfl_xor_sync(0xffffffffu, sum1, 2, 4);
            const float ri0 = 1.0f / sum0, ri1 = 1.0f / sum1;
            __half* s_p = s_u + ahh * (64 * HP);
            #pragma unroll
            for (int nt = 0; nt < 8; nt++) {
                const int c = nt * 8 + 2 * tg;
                *(__half2*)&s_p[row0 * HP + c] =
                    __floats2half2_rn(sacc[nt][0] * ri0, sacc[nt][1] * ri0);
                *(__half2*)&s_p[row1 * HP + c] =
                    __floats2half2_rn(sacc[nt][2] * ri1, sacc[nt][3] * ri1);
            }
        }
        __syncthreads();

        // ======= O_head[16rows,32] = P @ v^T ; store half to s_o ===========
        {
            float oacc[4][4];
            #pragma unroll
            for (int nt = 0; nt < 4; nt++) {
                oacc[nt][0] = 0.f; oacc[nt][1] = 0.f;
                oacc[nt][2] = 0.f; oacc[nt][3] = 0.f;
            }
            const __half* s_p = s_u + ahh * (64 * HP);
            #pragma unroll
            for (int kk = 0; kk < 4; kk++) {
                const int k0 = kk * 16;
                uint32_t a0 = ldh2(&s_p[(R + g) * HP + k0 + 2 * tg]);
                uint32_t a1 = ldh2(&s_p[(R + 8 + g) * HP + k0 + 2 * tg]);
                uint32_t a2 = ldh2(&s_p[(R + g) * HP + k0 + 2 * tg + 8]);
                uint32_t a3 = ldh2(&s_p[(R + 8 + g) * HP + k0 + 2 * tg + 8]);
                #pragma unroll
                for (int nt = 0; nt < 4; nt++) {
                    const int vr = ahh * 32 + nt * 8 + g;
                    uint32_t b0 = ldh2(&s_v[vr * HV + k0 + 2 * tg]);
                    uint32_t b1 = ldh2(&s_v[vr * HV + k0 + 2 * tg + 8]);
                    mma16(oacc[nt], a0, a1, a2, a3, b0, b1);
                }
            }
            const int row0 = R + g, row1 = R + 8 + g;
            const int cb = (h0 + ahh) * 32;
            #pragma unroll
            for (int nt = 0; nt < 4; nt++) {
                const int c = cb + nt * 8 + 2 * tg;
                if (row0 < 49)
                    *(__half2*)&s_o[row0 * HO + c] =
                        __floats2half2_rn(oacc[nt][0], oacc[nt][1]);
                if (row1 < 49)
                    *(__half2*)&s_o[row1 * HO + c] =
                        __floats2half2_rn(oacc[nt][2], oacc[nt][3]);
            }
        }
        __syncthreads();   // P reads + O writes done before s_u / qkv reuse
    } // head pairs

    // ======= proj: out = O[64,256] @ Wp[256,256] + b ========================
    {
        float facc[2][8][4];
        #pragma unroll
        for (int mt = 0; mt < 2; mt++)
            #pragma unroll
            for (int j = 0; j < 8; j++) {
                facc[mt][j][0] = 0.f; facc[mt][j][1] = 0.f;
                facc[mt][j][2] = 0.f; facc[mt][j][3] = 0.f;
            }
        for (int kc = 0; kc < 8; kc++) {
            __syncthreads();
            // stage Wp^T chunk [256 n][32 k]
            #pragma unroll
            for (int i = 0; i < 4; i++) {
                int idx = tid + i * 256;          // 0..1023
                int n = idx >> 2, c8 = idx & 3;
                uint4 v = *(const uint4*)&g_wph[n * 256 + kc * 32 + c8 * 8];
                *(uint4*)&s_u[n * HWP + c8 * 8] = v;
            }
            __syncthreads();
            #pragma unroll
            for (int kk = 0; kk < 2; kk++) {
                const int k0 = kc * 32 + kk * 16;
                const int kl = kk * 16;
                uint32_t a[2][4];
                #pragma unroll
                for (int mt = 0; mt < 2; mt++) {
                    const int r0 = mi * 32 + mt * 16 + g;
                    const int rc0 = (r0 < 49) ? r0 : 48;
                    const int rc1 = (r0 + 8 < 49) ? r0 + 8 : 48;
                    a[mt][0] = ldh2(&s_o[rc0 * HO + k0 + 2 * tg]);
                    a[mt][1] = ldh2(&s_o[rc1 * HO + k0 + 2 * tg]);
                    a[mt][2] = ldh2(&s_o[rc0 * HO + k0 + 2 * tg + 8]);
                    a[mt][3] = ldh2(&s_o[rc1 * HO + k0 + 2 * tg + 8]);
                }
                #pragma unroll
                for (int nt = 0; nt < 8; nt++) {
                    const int n = nb * 64 + nt * 8 + g;
                    uint32_t b0 = ldh2(&s_u[n * HWP + kl + 2 * tg]);
                    uint32_t b1 = ldh2(&s_u[n * HWP + kl + 2 * tg + 8]);
                    mma16(facc[0][nt], a[0][0], a[0][1], a[0][2], a[0][3], b0, b1);
                    mma16(facc[1][nt], a[1][0], a[1][1], a[1][2], a[1][3], b0, b1);
                }
            }
        }
        // epilogue
        float* ob = out + (size_t)b * (NTOK * DIMC);
        #pragma unroll
        for (int mt = 0; mt < 2; mt++) {
            const int r0 = mi * 32 + mt * 16 + g, r1 = r0 + 8;
            #pragma unroll
            for (int nt = 0; nt < 8; nt++) {
                const int c = nb * 64 + nt * 8 + 2 * tg;
                if (r0 < NTOK) {
                    float2 v;
                    v.x = facc[mt][nt][0] + s_pb[c];
                    v.y = facc[mt][nt][1] + s_pb[c + 1];
                    *(float2*)(ob + r0 * DIMC + c) = v;
                }
                if (r1 < NTOK) {
                    float2 v;
                    v.x = facc[mt][nt][2] + s_pb[c];
                    v.y = facc[mt][nt][3] + s_pb[c + 1];
                    *(float2*)(ob + r1 * DIMC + c) = v;
                }
            }
        }
    }
}

extern "C" void kernel_launch(void* const* d_in, const int* in_sizes, int n_in,
                              void* d_out, int out_size) {
    (void)in_sizes; (void)n_in; (void)out_size;
    const float* x      = (const float*)d_in[0];
    const float* qkv_w  = (const float*)d_in[1];
    const float* proj_w = (const float*)d_in[2];
    const float* proj_b = (const float*)d_in[3];
    const float* bt     = (const float*)d_in[4];
    const int*   ri     = (const int*)d_in[5];
    float* out = (float*)d_out;

    conv_w_kernel<<<128, 256>>>(qkv_w, proj_w);
    cudaFuncSetAttribute(win_attn_kernel,
                         cudaFuncAttributeMaxDynamicSharedMemorySize, SMEM_BYTES);
    win_attn_kernel<<<4096, 256, SMEM_BYTES>>>(x, proj_b, bt, ri, out);
}

// round 10
// speedup vs baseline: 2.6055x; 1.2526x over previous
#include <cuda_runtime.h>
#include <cuda_fp16.h>
#include <cstdint>

// ---------------------------------------------------------------------------
// WindowAttention fused (1 CTA = 1 window), FP16 mma m16n8k16 (f32 acc).
// R10: R9 design with the GEMM1 weight-prefetch section-stride fix
// (global q/k/v sections are 256 apart in g_w1h, local smem sections 64).
// ---------------------------------------------------------------------------

constexpr int NTOK = 49;
constexpr int DIMC = 256;

// strides in halves (all byte-strides multiples of 16B)
constexpr int HX  = 264;
constexpr int HQ  = 72;
constexpr int HK  = 72;
constexpr int HV  = 72;   // v^T [dim][token]
constexpr int HO  = 264;
constexpr int HW1 = 40;   // W1^T chunk [192 n][32 k]
constexpr int HWP = 40;   // Wp^T chunk [256 n][32 k]

constexpr int OFF_X = 0;                 // 49*264 = 12936
constexpr int OFF_Q = 12944;
constexpr int OFF_K = OFF_Q + 64 * HQ;   // 17552
constexpr int OFF_V = OFF_K + 64 * HK;   // 22160
constexpr int OFF_O = OFF_V + 64 * HV;   // 26768
constexpr int OFF_U = 39712;             // after O (39704), 16B aligned
constexpr int HALVES = OFF_U + 10240;
constexpr int SMEM_BYTES = HALVES * 2 + 1360 * 4 + 256 * 4 + 2432;  // 108800

__device__ __half g_w1h[768 * 256];   // [n][k] transposed qkv_w
__device__ __half g_wph[256 * 256];   // [n][k] transposed proj_w

__global__ void conv_w_kernel(const float* __restrict__ qkv_w,
                              const float* __restrict__ proj_w) {
    int t = blockIdx.x * blockDim.x + threadIdx.x;
    if (t < 768 * 32) {
        int n = t >> 5, kb = (t & 31) * 8;
        __half h[8];
        #pragma unroll
        for (int j = 0; j < 8; j++)
            h[j] = __float2half_rn(qkv_w[(size_t)(kb + j) * 768 + n]);
        *(uint4*)&g_w1h[n * 256 + kb] = *(uint4*)h;
    } else {
        int u = t - 768 * 32;
        int n = u >> 5, kb = (u & 31) * 8;
        __half h[8];
        #pragma unroll
        for (int j = 0; j < 8; j++)
            h[j] = __float2half_rn(proj_w[(size_t)(kb + j) * 256 + n]);
        *(uint4*)&g_wph[n * 256 + kb] = *(uint4*)h;
    }
}

__device__ __forceinline__ void mma16(float c[4],
                                      uint32_t a0, uint32_t a1, uint32_t a2, uint32_t a3,
                                      uint32_t b0, uint32_t b1) {
    asm volatile(
        "mma.sync.aligned.m16n8k16.row.col.f32.f16.f16.f32 "
        "{%0,%1,%2,%3}, {%4,%5,%6,%7}, {%8,%9}, {%0,%1,%2,%3};"
        : "+f"(c[0]), "+f"(c[1]), "+f"(c[2]), "+f"(c[3])
        : "r"(a0), "r"(a1), "r"(a2), "r"(a3), "r"(b0), "r"(b1));
}
__device__ __forceinline__ void ldsm4(uint32_t r[4], uint32_t a) {
    asm volatile("ldmatrix.sync.aligned.m8n8.x4.shared.b16 {%0,%1,%2,%3}, [%4];"
        : "=r"(r[0]), "=r"(r[1]), "=r"(r[2]), "=r"(r[3]) : "r"(a));
}
__device__ __forceinline__ uint32_t packh2(float x, float y) {
    __half2 h = __floats2half2_rn(x, y);
    return *(uint32_t*)&h;
}

__global__ void __launch_bounds__(256, 2)
win_attn_kernel(const float* __restrict__ x,
                const float* __restrict__ proj_b,
                const float* __restrict__ bias_table,
                const int*   __restrict__ rel_idx,
                float*       __restrict__ out) {
    extern __shared__ __half sh[];
    __half* s_x = sh + OFF_X;
    __half* s_q = sh + OFF_Q;
    __half* s_k = sh + OFF_K;
    __half* s_v = sh + OFF_V;
    __half* s_o = sh + OFF_O;
    __half* s_u = sh + OFF_U;
    float* s_bt2 = (float*)((char*)sh + HALVES * 2);   // [head][170]
    float* s_pb  = s_bt2 + 1360;
    unsigned char* s_ri = (unsigned char*)(s_pb + 256);
    const uint32_t sb = (uint32_t)__cvta_generic_to_shared(sh);

    const int tid  = threadIdx.x;
    const int w    = tid >> 5;
    const int lane = tid & 31;
    const int g    = lane >> 2;
    const int tg   = lane & 3;
    const int b    = blockIdx.x;

    const int mi = w & 1;          // GEMM1/proj 32-row block
    const int nb = w >> 1;         // GEMM1/proj N block
    const int ahh = w >> 2;        // attention: head within pair
    const int R   = (w & 3) * 16;  // attention: row base

    // ldmatrix lane decomposition
    const int arow_in = (lane & 7) | (((lane >> 3) & 1) << 3);
    const int acol8   = (lane >> 4) << 3;
    const int brow_in = (lane & 7) | (((lane >> 4) & 1) << 3);
    const int bcol8   = ((lane >> 3) & 1) << 3;

    // ---- init: stage x (f32->half), tables ----
    {
        const float4* x4 = (const float4*)(x + (size_t)b * (NTOK * DIMC));
        #pragma unroll
        for (int i = 0; i < 13; i++) {
            int idx = tid + i * 256;
            if (idx < 3136) {
                int r = idx >> 6, c4 = idx & 63;
                float4 v = x4[idx];
                __half2* dst = (__half2*)&s_x[r * HX + c4 * 4];
                dst[0] = __floats2half2_rn(v.x, v.y);
                dst[1] = __floats2half2_rn(v.z, v.w);
            }
        }
        for (int i = tid; i < 2401; i += 256) s_ri[i] = (unsigned char)rel_idx[i];
        for (int i = tid; i < 1352; i += 256)
            s_bt2[(i & 7) * 170 + (i >> 3)] = bias_table[i];
        if (tid < 256) s_pb[tid] = proj_b[tid];
    }
    __syncthreads();

    const float scale = 0.17677669529663687f;  // 1/sqrt(32)

    // precomputed byte addresses
    uint32_t aXb[2];
    #pragma unroll
    for (int mt = 0; mt < 2; mt++) {
        int r = mi * 32 + mt * 16 + arow_in;
        int rc = (r < 49) ? r : 48;
        aXb[mt] = sb + 2 * (OFF_X + rc * HX + acol8);
    }
    uint32_t bW1[3];
    #pragma unroll
    for (int nf = 0; nf < 3; nf++)
        bW1[nf] = sb + 2 * (OFF_U + (nb * 48 + nf * 16 + brow_in) * HW1 + bcol8);
    const uint32_t aQb = sb + 2 * (OFF_Q + (R + arow_in) * HQ + ahh * 32 + acol8);
    uint32_t bKb[4];
    #pragma unroll
    for (int nf = 0; nf < 4; nf++)
        bKb[nf] = sb + 2 * (OFF_K + (nf * 16 + brow_in) * HK + ahh * 32 + bcol8);
    uint32_t bVb[2];
    #pragma unroll
    for (int nf = 0; nf < 2; nf++)
        bVb[nf] = sb + 2 * (OFF_V + (ahh * 32 + nf * 16 + brow_in) * HV + bcol8);
    uint32_t aOb[2];
    #pragma unroll
    for (int mt = 0; mt < 2; mt++) {
        int r = mi * 32 + mt * 16 + arow_in;
        int rc = (r < 49) ? r : 48;
        aOb[mt] = sb + 2 * (OFF_O + rc * HO + acol8);
    }
    uint32_t bWP[4];
    #pragma unroll
    for (int nf = 0; nf < 4; nf++)
        bWP[nf] = sb + 2 * (OFF_U + (nb * 64 + nf * 16 + brow_in) * HWP + bcol8);

    for (int hp = 0; hp < 4; hp++) {
        const int h0 = 2 * hp;

        // ======= GEMM1: qkv_pair[64,192] = x @ W1 (prefetched staging) =====
        float acc1[2][6][4];
        #pragma unroll
        for (int mt = 0; mt < 2; mt++)
            #pragma unroll
            for (int nt = 0; nt < 6; nt++) {
                acc1[mt][nt][0] = 0.f; acc1[mt][nt][1] = 0.f;
                acc1[mt][nt][2] = 0.f; acc1[mt][nt][3] = 0.f;
            }
        {
            const int pn = tid >> 2, pc8 = tid & 3;       // pn 0..63
            const int phh = (pn >> 5) & 1, pd = pn & 31;
            const int pgn = (h0 + phh) * 32 + pd;          // global n within section
            uint4 pf[3];
            #pragma unroll
            for (int i = 0; i < 3; i++)   // sections q/k/v are 256 apart globally
                pf[i] = *(const uint4*)&g_w1h[(size_t)(pgn + i * 256) * 256 + pc8 * 8];
            for (int kc = 0; kc < 8; kc++) {
                __syncthreads();   // prior readers of s_u done
                #pragma unroll
                for (int i = 0; i < 3; i++)
                    *(uint4*)&s_u[(pn + i * 64) * HW1 + pc8 * 8] = pf[i];
                if (kc < 7) {
                    #pragma unroll
                    for (int i = 0; i < 3; i++)
                        pf[i] = *(const uint4*)&g_w1h[(size_t)(pgn + i * 256) * 256 +
                                                      (kc + 1) * 32 + pc8 * 8];
                }
                __syncthreads();
                #pragma unroll
                for (int kk = 0; kk < 2; kk++) {
                    const uint32_t koff = (kc * 32 + kk * 16) * 2;
                    const uint32_t kl = kk * 32;
                    uint32_t a[2][4], bfr[3][4];
                    ldsm4(a[0], aXb[0] + koff);
                    ldsm4(a[1], aXb[1] + koff);
                    ldsm4(bfr[0], bW1[0] + kl);
                    ldsm4(bfr[1], bW1[1] + kl);
                    ldsm4(bfr[2], bW1[2] + kl);
                    #pragma unroll
                    for (int nt = 0; nt < 6; nt++) {
                        uint32_t b0 = bfr[nt >> 1][(nt & 1) * 2];
                        uint32_t b1 = bfr[nt >> 1][(nt & 1) * 2 + 1];
                        mma16(acc1[0][nt], a[0][0], a[0][1], a[0][2], a[0][3], b0, b1);
                        mma16(acc1[1][nt], a[1][0], a[1][1], a[1][2], a[1][3], b0, b1);
                    }
                }
            }
        }
        // scatter q (scaled) / k / v^T
        #pragma unroll
        for (int mt = 0; mt < 2; mt++) {
            const int r0 = mi * 32 + mt * 16 + g, r1 = r0 + 8;
            #pragma unroll
            for (int nt = 0; nt < 6; nt++) {
                const int colb = nb * 48 + nt * 8;
                const int s = colb >> 6;
                const int cc = (colb & 63) + 2 * tg;
                if (s == 0) {
                    *(__half2*)&s_q[r0 * HQ + cc] =
                        __floats2half2_rn(acc1[mt][nt][0] * scale, acc1[mt][nt][1] * scale);
                    *(__half2*)&s_q[r1 * HQ + cc] =
                        __floats2half2_rn(acc1[mt][nt][2] * scale, acc1[mt][nt][3] * scale);
                } else if (s == 1) {
                    *(__half2*)&s_k[r0 * HK + cc] =
                        __floats2half2_rn(acc1[mt][nt][0], acc1[mt][nt][1]);
                    *(__half2*)&s_k[r1 * HK + cc] =
                        __floats2half2_rn(acc1[mt][nt][2], acc1[mt][nt][3]);
                } else {
                    s_v[cc * HV + r0]       = __float2half_rn(acc1[mt][nt][0]);
                    s_v[(cc + 1) * HV + r0] = __float2half_rn(acc1[mt][nt][1]);
                    s_v[cc * HV + r1]       = __float2half_rn(acc1[mt][nt][2]);
                    s_v[(cc + 1) * HV + r1] = __float2half_rn(acc1[mt][nt][3]);
                }
            }
        }
        __syncthreads();

        // ======= scores: warp = 16 rows x 64 cols of one head ==============
        float sacc[8][4];
        #pragma unroll
        for (int nt = 0; nt < 8; nt++) {
            sacc[nt][0] = 0.f; sacc[nt][1] = 0.f;
            sacc[nt][2] = 0.f; sacc[nt][3] = 0.f;
        }
        #pragma unroll
        for (int kk = 0; kk < 2; kk++) {
            const uint32_t kl = kk * 32;
            uint32_t a[4], bfr[4][4];
            ldsm4(a, aQb + kl);
            ldsm4(bfr[0], bKb[0] + kl);
            ldsm4(bfr[1], bKb[1] + kl);
            ldsm4(bfr[2], bKb[2] + kl);
            ldsm4(bfr[3], bKb[3] + kl);
            #pragma unroll
            for (int nt = 0; nt < 8; nt++)
                mma16(sacc[nt], a[0], a[1], a[2], a[3],
                      bfr[nt >> 1][(nt & 1) * 2], bfr[nt >> 1][(nt & 1) * 2 + 1]);
        }

        // ======= softmax in registers; P stays in registers ================
        uint32_t pa[4][4];
        {
            const int head = h0 + ahh;
            const int row0 = R + g, row1 = R + 8 + g;
            const int rs0 = (row0 < 49) ? row0 : 48;
            const int rs1 = (row1 < 49) ? row1 : 48;
            const unsigned char* rr0 = s_ri + rs0 * 49;
            const unsigned char* rr1 = s_ri + rs1 * 49;
            const float* btH = s_bt2 + head * 170;
            float mx0 = -1e30f, mx1 = -1e30f;
            #pragma unroll
            for (int nt = 0; nt < 8; nt++) {
                const int c0 = nt * 8 + 2 * tg, c1 = c0 + 1;
                float v;
                v = (c0 < 49) ? sacc[nt][0] + btH[rr0[c0 < 49 ? c0 : 0]] : -1e30f;
                sacc[nt][0] = v; mx0 = fmaxf(mx0, v);
                v = (c1 < 49) ? sacc[nt][1] + btH[rr0[c1 < 49 ? c1 : 0]] : -1e30f;
                sacc[nt][1] = v; mx0 = fmaxf(mx0, v);
                v = (c0 < 49) ? sacc[nt][2] + btH[rr1[c0 < 49 ? c0 : 0]] : -1e30f;
                sacc[nt][2] = v; mx1 = fmaxf(mx1, v);
                v = (c1 < 49) ? sacc[nt][3] + btH[rr1[c1 < 49 ? c1 : 0]] : -1e30f;
                sacc[nt][3] = v; mx1 = fmaxf(mx1, v);
            }
            mx0 = fmaxf(mx0, __shfl_xor_sync(0xffffffffu, mx0, 1, 4));
            mx0 = fmaxf(mx0, __shfl_xor_sync(0xffffffffu, mx0, 2, 4));
            mx1 = fmaxf(mx1, __shfl_xor_sync(0xffffffffu, mx1, 1, 4));
            mx1 = fmaxf(mx1, __shfl_xor_sync(0xffffffffu, mx1, 2, 4));
            float sum0 = 0.f, sum1 = 0.f;
            #pragma unroll
            for (int nt = 0; nt < 8; nt++) {
                float e;
                e = __expf(sacc[nt][0] - mx0); sacc[nt][0] = e; sum0 += e;
                e = __expf(sacc[nt][1] - mx0); sacc[nt][1] = e; sum0 += e;
                e = __expf(sacc[nt][2] - mx1); sacc[nt][2] = e; sum1 += e;
                e = __expf(sacc[nt][3] - mx1); sacc[nt][3] = e; sum1 += e;
            }
            sum0 += __shfl_xor_sync(0xffffffffu, sum0, 1, 4);
            sum0 += __shfl_xor_sync(0xffffffffu, sum0, 2, 4);
            sum1 += __shfl_xor_sync(0xffffffffu, sum1, 1, 4);
            sum1 += __shfl_xor_sync(0xffffffffu, sum1, 2, 4);
            const float ri0 = 1.0f / sum0, ri1 = 1.0f / sum1;
            #pragma unroll
            for (int kk = 0; kk < 4; kk++) {
                pa[kk][0] = packh2(sacc[2 * kk][0] * ri0, sacc[2 * kk][1] * ri0);
                pa[kk][1] = packh2(sacc[2 * kk][2] * ri1, sacc[2 * kk][3] * ri1);
                pa[kk][2] = packh2(sacc[2 * kk + 1][0] * ri0, sacc[2 * kk + 1][1] * ri0);
                pa[kk][3] = packh2(sacc[2 * kk + 1][2] * ri1, sacc[2 * kk + 1][3] * ri1);
            }
        }

        // ======= O = P @ v^T (P in regs) ; store half to s_o ===============
        {
            float oacc[4][4];
            #pragma unroll
            for (int nt = 0; nt < 4; nt++) {
                oacc[nt][0] = 0.f; oacc[nt][1] = 0.f;
                oacc[nt][2] = 0.f; oacc[nt][3] = 0.f;
            }
            #pragma unroll
            for (int kk = 0; kk < 4; kk++) {
                const uint32_t kl = kk * 32;
                uint32_t bfr[2][4];
                ldsm4(bfr[0], bVb[0] + kl);
                ldsm4(bfr[1], bVb[1] + kl);
                #pragma unroll
                for (int nt = 0; nt < 4; nt++)
                    mma16(oacc[nt], pa[kk][0], pa[kk][1], pa[kk][2], pa[kk][3],
                          bfr[nt >> 1][(nt & 1) * 2], bfr[nt >> 1][(nt & 1) * 2 + 1]);
            }
            const int row0 = R + g, row1 = R + 8 + g;
            const int cb = (h0 + ahh) * 32;
            #pragma unroll
            for (int nt = 0; nt < 4; nt++) {
                const int c = cb + nt * 8 + 2 * tg;
                if (row0 < 49)
                    *(__half2*)&s_o[row0 * HO + c] =
                        __floats2half2_rn(oacc[nt][0], oacc[nt][1]);
                if (row1 < 49)
                    *(__half2*)&s_o[row1 * HO + c] =
                        __floats2half2_rn(oacc[nt][2], oacc[nt][3]);
            }
        }
    } // head pairs
    __syncthreads();

    // ======= proj: out = O[64,256] @ Wp + b (prefetched staging) ===========
    {
        float facc[2][8][4];
        #pragma unroll
        for (int mt = 0; mt < 2; mt++)
            #pragma unroll
            for (int j = 0; j < 8; j++) {
                facc[mt][j][0] = 0.f; facc[mt][j][1] = 0.f;
                facc[mt][j][2] = 0.f; facc[mt][j][3] = 0.f;
            }
        const int pn = tid >> 2, pc8 = tid & 3;
        uint4 pf[4];
        #pragma unroll
        for (int i = 0; i < 4; i++)
            pf[i] = *(const uint4*)&g_wph[(size_t)(pn + i * 64) * 256 + pc8 * 8];
        for (int kc = 0; kc < 8; kc++) {
            __syncthreads();
            #pragma unroll
            for (int i = 0; i < 4; i++)
                *(uint4*)&s_u[(pn + i * 64) * HWP + pc8 * 8] = pf[i];
            if (kc < 7) {
                #pragma unroll
                for (int i = 0; i < 4; i++)
                    pf[i] = *(const uint4*)&g_wph[(size_t)(pn + i * 64) * 256 +
                                                  (kc + 1) * 32 + pc8 * 8];
            }
            __syncthreads();
            #pragma unroll
            for (int kk = 0; kk < 2; kk++) {
                const uint32_t koff = (kc * 32 + kk * 16) * 2;
                const uint32_t kl = kk * 32;
                uint32_t a[2][4], bfr[4][4];
                ldsm4(a[0], aOb[0] + koff);
                ldsm4(a[1], aOb[1] + koff);
                ldsm4(bfr[0], bWP[0] + kl);
                ldsm4(bfr[1], bWP[1] + kl);
                ldsm4(bfr[2], bWP[2] + kl);
                ldsm4(bfr[3], bWP[3] + kl);
                #pragma unroll
                for (int nt = 0; nt < 8; nt++) {
                    uint32_t b0 = bfr[nt >> 1][(nt & 1) * 2];
                    uint32_t b1 = bfr[nt >> 1][(nt & 1) * 2 + 1];
                    mma16(facc[0][nt], a[0][0], a[0][1], a[0][2], a[0][3], b0, b1);
                    mma16(facc[1][nt], a[1][0], a[1][1], a[1][2], a[1][3], b0, b1);
                }
            }
        }
        // epilogue
        float* ob = out + (size_t)b * (NTOK * DIMC);
        #pragma unroll
        for (int mt = 0; mt < 2; mt++) {
            const int r0 = mi * 32 + mt * 16 + g, r1 = r0 + 8;
            #pragma unroll
            for (int nt = 0; nt < 8; nt++) {
                const int c = nb * 64 + nt * 8 + 2 * tg;
                if (r0 < NTOK) {
                    float2 v;
                    v.x = facc[mt][nt][0] + s_pb[c];
                    v.y = facc[mt][nt][1] + s_pb[c + 1];
                    *(float2*)(ob + r0 * DIMC + c) = v;
                }
                if (r1 < NTOK) {
                    float2 v;
                    v.x = facc[mt][nt][2] + s_pb[c];
                    v.y = facc[mt][nt][3] + s_pb[c + 1];
                    *(float2*)(ob + r1 * DIMC + c) = v;
                }
            }
        }
    }
}

extern "C" void kernel_launch(void* const* d_in, const int* in_sizes, int n_in,
                              void* d_out, int out_size) {
    (void)in_sizes; (void)n_in; (void)out_size;
    const float* x      = (const float*)d_in[0];
    const float* qkv_w  = (const float*)d_in[1];
    const float* proj_w = (const float*)d_in[2];
    const float* proj_b = (const float*)d_in[3];
    const float* bt     = (const float*)d_in[4];
    const int*   ri     = (const int*)d_in[5];
    float* out = (float*)d_out;

    conv_w_kernel<<<128, 256>>>(qkv_w, proj_w);
    cudaFuncSetAttribute(win_attn_kernel,
                         cudaFuncAttributeMaxDynamicSharedMemorySize, SMEM_BYTES);
    win_attn_kernel<<<4096, 256, SMEM_BYTES>>>(x, proj_b, bt, ri, out);
}

// round 11
// speedup vs baseline: 3.4851x; 1.3376x over previous
#include <cuda_runtime.h>
#include <cuda_fp16.h>
#include <cstdint>

// ---------------------------------------------------------------------------
// WindowAttention fused (1 CTA = 1 window), FP16 mma m16n8k16 (f32 acc).
// R11: GEMM1 weight-B fragments streamed directly from L2 in fragment order
// (prologue-packed g_w1f), bias matrix pre-materialized (no smem gathers).
// ---------------------------------------------------------------------------

constexpr int NTOK = 49;
constexpr int DIMC = 256;

// strides in halves
constexpr int HX  = 264;
constexpr int HQ  = 72;
constexpr int HK  = 72;
constexpr int HV  = 72;   // v^T [dim][token]
constexpr int HO  = 264;
constexpr int HWP = 40;   // Wp^T chunk [256 n][32 k]

constexpr int OFF_X = 0;                 // 49*264 = 12936
constexpr int OFF_Q = 12944;
constexpr int OFF_K = OFF_Q + 64 * HQ;   // 17552
constexpr int OFF_V = OFF_K + 64 * HK;   // 22160
constexpr int OFF_O = OFF_V + 64 * HV;   // 26768
constexpr int OFF_U = 39712;             // Wp staging (after O at 39704)
constexpr int HALVES = OFF_U + 10240;    // 49952
constexpr int SMEM_BYTES = HALVES * 2 + 256 * 4;   // + proj_b -> 100928 B

// W1 fragments in consumption order:
// block (hp,kc,kk,nb,nf) of 32 uint4; lane l's uint4 = its 4 ldmatrix regs.
__device__ uint4  g_w1f[4 * 8 * 2 * 4 * 3 * 32];   // 384 KB
__device__ __half g_wph[256 * 256];                 // proj W^T [n][k], 128 KB
__device__ float  g_biasf[8 * 49 * 64];             // bias[h][row][col], 100 KB

__global__ void prep_kernel(const float* __restrict__ qkv_w,
                            const float* __restrict__ proj_w,
                            const float* __restrict__ bias_table,
                            const int*   __restrict__ rel_idx) {
    int t = blockIdx.x * blockDim.x + threadIdx.x;
    if (t < 24576) {
        // --- W1 fragment packing ---
        int lane = t & 31;
        int r2 = t >> 5;
        int nf = r2 % 3;  int r3 = r2 / 3;
        int nb = r3 & 3;  int r4 = r3 >> 2;
        int kk = r4 & 1;  int r5 = r4 >> 1;
        int kc = r5 & 7;  int hp = r5 >> 3;
        int h0 = 2 * hp;
        uint32_t wr[4];
        #pragma unroll
        for (int t4 = 0; t4 < 4; t4++) {
            int rowt = (t4 & 2) ? 8 : 0;
            int coft = (t4 & 1) ? 8 : 0;
            int r  = nb * 48 + nf * 16 + rowt + (lane >> 2);   // 0..191 pair-col
            int gn = (r >> 6) * 256 + (h0 + ((r & 63) >> 5)) * 32 + (r & 31);
            int k  = kc * 32 + kk * 16 + coft + 2 * (lane & 3);
            __half2 hv = __floats2half2_rn(qkv_w[(size_t)k * 768 + gn],
                                           qkv_w[(size_t)(k + 1) * 768 + gn]);
            wr[t4] = *(uint32_t*)&hv;
        }
        g_w1f[t] = make_uint4(wr[0], wr[1], wr[2], wr[3]);
    } else if (t < 24576 + 8192) {
        // --- proj W^T [n][k] half ---
        int u = t - 24576;
        int n = u >> 5, kb = (u & 31) * 8;
        __half h[8];
        #pragma unroll
        for (int j = 0; j < 8; j++)
            h[j] = __float2half_rn(proj_w[(size_t)(kb + j) * 256 + n]);
        *(uint4*)&g_wph[n * 256 + kb] = *(uint4*)h;
    } else {
        // --- bias matrix ---
        int u = t - 32768;
        if (u < 25088) {
            int h = u / 3136, rem = u % 3136;
            int r = rem >> 6, c = rem & 63;
            g_biasf[u] = (c < 49)
                ? bias_table[rel_idx[r * 49 + c] * 8 + h]
                : -30000.0f;
        }
    }
}

__device__ __forceinline__ void mma16(float c[4],
                                      uint32_t a0, uint32_t a1, uint32_t a2, uint32_t a3,
                                      uint32_t b0, uint32_t b1) {
    asm volatile(
        "mma.sync.aligned.m16n8k16.row.col.f32.f16.f16.f32 "
        "{%0,%1,%2,%3}, {%4,%5,%6,%7}, {%8,%9}, {%0,%1,%2,%3};"
        : "+f"(c[0]), "+f"(c[1]), "+f"(c[2]), "+f"(c[3])
        : "r"(a0), "r"(a1), "r"(a2), "r"(a3), "r"(b0), "r"(b1));
}
__device__ __forceinline__ void ldsm4(uint32_t r[4], uint32_t a) {
    asm volatile("ldmatrix.sync.aligned.m8n8.x4.shared.b16 {%0,%1,%2,%3}, [%4];"
        : "=r"(r[0]), "=r"(r[1]), "=r"(r[2]), "=r"(r[3]) : "r"(a));
}
__device__ __forceinline__ uint32_t packh2(float x, float y) {
    __half2 h = __floats2half2_rn(x, y);
    return *(uint32_t*)&h;
}

__global__ void __launch_bounds__(256, 2)
win_attn_kernel(const float* __restrict__ x,
                const float* __restrict__ proj_b,
                float*       __restrict__ out) {
    extern __shared__ __half sh[];
    __half* s_x = sh + OFF_X;
    __half* s_q = sh + OFF_Q;
    __half* s_k = sh + OFF_K;
    __half* s_v = sh + OFF_V;
    __half* s_o = sh + OFF_O;
    __half* s_u = sh + OFF_U;
    float* s_pb = (float*)((char*)sh + HALVES * 2);
    const uint32_t sb = (uint32_t)__cvta_generic_to_shared(sh);

    const int tid  = threadIdx.x;
    const int w    = tid >> 5;
    const int lane = tid & 31;
    const int g    = lane >> 2;
    const int tg   = lane & 3;
    const int b    = blockIdx.x;

    const int mi = w & 1;          // GEMM1/proj 32-row block
    const int nb = w >> 1;         // GEMM1/proj N block
    const int ahh = w >> 2;        // attention: head within pair
    const int R   = (w & 3) * 16;  // attention: row base

    // ldmatrix lane decomposition
    const int arow_in = (lane & 7) | (((lane >> 3) & 1) << 3);
    const int acol8   = (lane >> 4) << 3;
    const int brow_in = (lane & 7) | (((lane >> 4) & 1) << 3);
    const int bcol8   = ((lane >> 3) & 1) << 3;

    // ---- init: stage x (f32->half), proj_b ----
    {
        const float4* x4 = (const float4*)(x + (size_t)b * (NTOK * DIMC));
        #pragma unroll
        for (int i = 0; i < 13; i++) {
            int idx = tid + i * 256;
            if (idx < 3136) {
                int r = idx >> 6, c4 = idx & 63;
                float4 v = x4[idx];
                __half2* dst = (__half2*)&s_x[r * HX + c4 * 4];
                dst[0] = __floats2half2_rn(v.x, v.y);
                dst[1] = __floats2half2_rn(v.z, v.w);
            }
        }
        if (tid < 256) s_pb[tid] = proj_b[tid];
    }
    __syncthreads();

    const float scale = 0.17677669529663687f;  // 1/sqrt(32)

    // precomputed byte addresses
    uint32_t aXb[2];
    #pragma unroll
    for (int mt = 0; mt < 2; mt++) {
        int r = mi * 32 + mt * 16 + arow_in;
        int rc = (r < 49) ? r : 48;
        aXb[mt] = sb + 2 * (OFF_X + rc * HX + acol8);
    }
    const uint32_t aQb = sb + 2 * (OFF_Q + (R + arow_in) * HQ + ahh * 32 + acol8);
    uint32_t bKb[4];
    #pragma unroll
    for (int nf = 0; nf < 4; nf++)
        bKb[nf] = sb + 2 * (OFF_K + (nf * 16 + brow_in) * HK + ahh * 32 + bcol8);
    uint32_t bVb[2];
    #pragma unroll
    for (int nf = 0; nf < 2; nf++)
        bVb[nf] = sb + 2 * (OFF_V + (ahh * 32 + nf * 16 + brow_in) * HV + bcol8);
    uint32_t aOb[2];
    #pragma unroll
    for (int mt = 0; mt < 2; mt++) {
        int r = mi * 32 + mt * 16 + arow_in;
        int rc = (r < 49) ? r : 48;
        aOb[mt] = sb + 2 * (OFF_O + rc * HO + acol8);
    }
    uint32_t bWP[4];
    #pragma unroll
    for (int nf = 0; nf < 4; nf++)
        bWP[nf] = sb + 2 * (OFF_U + (nb * 64 + nf * 16 + brow_in) * HWP + bcol8);

    for (int hp = 0; hp < 4; hp++) {
        const int h0 = 2 * hp;

        // ======= GEMM1: qkv_pair[64,192] = x @ W1, B streamed from L2 ======
        float acc1[2][6][4];
        #pragma unroll
        for (int mt = 0; mt < 2; mt++)
            #pragma unroll
            for (int nt = 0; nt < 6; nt++) {
                acc1[mt][nt][0] = 0.f; acc1[mt][nt][1] = 0.f;
                acc1[mt][nt][2] = 0.f; acc1[mt][nt][3] = 0.f;
            }
        {
            // fragment stream base: blocks of 32 uint4; i = kc*2+kk
            const uint4* wp = g_w1f + (size_t)hp * (16 * 384) + nb * 96 + lane;
            uint4 bv0 = wp[0], bv1 = wp[32], bv2 = wp[64];
            #pragma unroll
            for (int i = 0; i < 16; i++) {
                uint4 nx0, nx1, nx2;
                if (i < 15) {
                    const uint4* np = wp + (i + 1) * 384;
                    nx0 = np[0]; nx1 = np[32]; nx2 = np[64];
                }
                uint32_t a[2][4];
                ldsm4(a[0], aXb[0] + i * 32);
                ldsm4(a[1], aXb[1] + i * 32);
                // nt 0..5 -> (bv[nt>>1], words (nt&1)*2, +1)
                mma16(acc1[0][0], a[0][0], a[0][1], a[0][2], a[0][3], bv0.x, bv0.y);
                mma16(acc1[1][0], a[1][0], a[1][1], a[1][2], a[1][3], bv0.x, bv0.y);
                mma16(acc1[0][1], a[0][0], a[0][1], a[0][2], a[0][3], bv0.z, bv0.w);
                mma16(acc1[1][1], a[1][0], a[1][1], a[1][2], a[1][3], bv0.z, bv0.w);
                mma16(acc1[0][2], a[0][0], a[0][1], a[0][2], a[0][3], bv1.x, bv1.y);
                mma16(acc1[1][2], a[1][0], a[1][1], a[1][2], a[1][3], bv1.x, bv1.y);
                mma16(acc1[0][3], a[0][0], a[0][1], a[0][2], a[0][3], bv1.z, bv1.w);
                mma16(acc1[1][3], a[1][0], a[1][1], a[1][2], a[1][3], bv1.z, bv1.w);
                mma16(acc1[0][4], a[0][0], a[0][1], a[0][2], a[0][3], bv2.x, bv2.y);
                mma16(acc1[1][4], a[1][0], a[1][1], a[1][2], a[1][3], bv2.x, bv2.y);
                mma16(acc1[0][5], a[0][0], a[0][1], a[0][2], a[0][3], bv2.z, bv2.w);
                mma16(acc1[1][5], a[1][0], a[1][1], a[1][2], a[1][3], bv2.z, bv2.w);
                if (i < 15) { bv0 = nx0; bv1 = nx1; bv2 = nx2; }
            }
        }
        // barrier: prior pair's scores/PV reads of s_q/k/v must be done
        __syncthreads();
        // scatter q (scaled) / k / v^T
        #pragma unroll
        for (int mt = 0; mt < 2; mt++) {
            const int r0 = mi * 32 + mt * 16 + g, r1 = r0 + 8;
            #pragma unroll
            for (int nt = 0; nt < 6; nt++) {
                const int colb = nb * 48 + nt * 8;
                const int s = colb >> 6;
                const int cc = (colb & 63) + 2 * tg;
                if (s == 0) {
                    *(__half2*)&s_q[r0 * HQ + cc] =
                        __floats2half2_rn(acc1[mt][nt][0] * scale, acc1[mt][nt][1] * scale);
                    *(__half2*)&s_q[r1 * HQ + cc] =
                        __floats2half2_rn(acc1[mt][nt][2] * scale, acc1[mt][nt][3] * scale);
                } else if (s == 1) {
                    *(__half2*)&s_k[r0 * HK + cc] =
                        __floats2half2_rn(acc1[mt][nt][0], acc1[mt][nt][1]);
                    *(__half2*)&s_k[r1 * HK + cc] =
                        __floats2half2_rn(acc1[mt][nt][2], acc1[mt][nt][3]);
                } else {
                    s_v[cc * HV + r0]       = __float2half_rn(acc1[mt][nt][0]);
                    s_v[(cc + 1) * HV + r0] = __float2half_rn(acc1[mt][nt][1]);
                    s_v[cc * HV + r1]       = __float2half_rn(acc1[mt][nt][2]);
                    s_v[(cc + 1) * HV + r1] = __float2half_rn(acc1[mt][nt][3]);
                }
            }
        }
        __syncthreads();

        // ======= scores: warp = 16 rows x 64 cols of one head ==============
        float sacc[8][4];
        #pragma unroll
        for (int nt = 0; nt < 8; nt++) {
            sacc[nt][0] = 0.f; sacc[nt][1] = 0.f;
            sacc[nt][2] = 0.f; sacc[nt][3] = 0.f;
        }
        #pragma unroll
        for (int kk = 0; kk < 2; kk++) {
            const uint32_t kl = kk * 32;
            uint32_t a[4], bfr[4][4];
            ldsm4(a, aQb + kl);
            ldsm4(bfr[0], bKb[0] + kl);
            ldsm4(bfr[1], bKb[1] + kl);
            ldsm4(bfr[2], bKb[2] + kl);
            ldsm4(bfr[3], bKb[3] + kl);
            #pragma unroll
            for (int nt = 0; nt < 8; nt++)
                mma16(sacc[nt], a[0], a[1], a[2], a[3],
                      bfr[nt >> 1][(nt & 1) * 2], bfr[nt >> 1][(nt & 1) * 2 + 1]);
        }

        // ======= softmax in registers; bias from L2-hot precomputed matrix =
        uint32_t pa[4][4];
        {
            const int head = h0 + ahh;
            const int row0 = R + g, row1 = R + 8 + g;
            const int rs0 = (row0 < 49) ? row0 : 48;
            const int rs1 = (row1 < 49) ? row1 : 48;
            const float* b0p = g_biasf + (head * 49 + rs0) * 64;
            const float* b1p = g_biasf + (head * 49 + rs1) * 64;
            float mx0 = -1e30f, mx1 = -1e30f;
            #pragma unroll
            for (int nt = 0; nt < 8; nt++) {
                const int c0 = nt * 8 + 2 * tg;
                float2 bA = *(const float2*)(b0p + c0);
                float2 bB = *(const float2*)(b1p + c0);
                float v;
                v = sacc[nt][0] + bA.x; sacc[nt][0] = v; mx0 = fmaxf(mx0, v);
                v = sacc[nt][1] + bA.y; sacc[nt][1] = v; mx0 = fmaxf(mx0, v);
                v = sacc[nt][2] + bB.x; sacc[nt][2] = v; mx1 = fmaxf(mx1, v);
                v = sacc[nt][3] + bB.y; sacc[nt][3] = v; mx1 = fmaxf(mx1, v);
            }
            mx0 = fmaxf(mx0, __shfl_xor_sync(0xffffffffu, mx0, 1, 4));
            mx0 = fmaxf(mx0, __shfl_xor_sync(0xffffffffu, mx0, 2, 4));
            mx1 = fmaxf(mx1, __shfl_xor_sync(0xffffffffu, mx1, 1, 4));
            mx1 = fmaxf(mx1, __shfl_xor_sync(0xffffffffu, mx1, 2, 4));
            float sum0 = 0.f, sum1 = 0.f;
            #pragma unroll
            for (int nt = 0; nt < 8; nt++) {
                float e;
                e = __expf(sacc[nt][0] - mx0); sacc[nt][0] = e; sum0 += e;
                e = __expf(sacc[nt][1] - mx0); sacc[nt][1] = e; sum0 += e;
                e = __expf(sacc[nt][2] - mx1); sacc[nt][2] = e; sum1 += e;
                e = __expf(sacc[nt][3] - mx1); sacc[nt][3] = e; sum1 += e;
            }
            sum0 += __shfl_xor_sync(0xffffffffu, sum0, 1, 4);
            sum0 += __shfl_xor_sync(0xffffffffu, sum0, 2, 4);
            sum1 += __shfl_xor_sync(0xffffffffu, sum1, 1, 4);
            sum1 += __shfl_xor_sync(0xffffffffu, sum1, 2, 4);
            const float ri0 = 1.0f / sum0, ri1 = 1.0f / sum1;
            #pragma unroll
            for (int kk = 0; kk < 4; kk++) {
                pa[kk][0] = packh2(sacc[2 * kk][0] * ri0, sacc[2 * kk][1] * ri0);
                pa[kk][1] = packh2(sacc[2 * kk][2] * ri1, sacc[2 * kk][3] * ri1);
                pa[kk][2] = packh2(sacc[2 * kk + 1][0] * ri0, sacc[2 * kk + 1][1] * ri0);
                pa[kk][3] = packh2(sacc[2 * kk + 1][2] * ri1, sacc[2 * kk + 1][3] * ri1);
            }
        }

        // ======= O = P @ v^T (P in regs) ; store half to s_o ===============
        {
            float oacc[4][4];
            #pragma unroll
            for (int nt = 0; nt < 4; nt++) {
                oacc[nt][0] = 0.f; oacc[nt][1] = 0.f;
                oacc[nt][2] = 0.f; oacc[nt][3] = 0.f;
            }
            #pragma unroll
            for (int kk = 0; kk < 4; kk++) {
                const uint32_t kl = kk * 32;
                uint32_t bfr[2][4];
                ldsm4(bfr[0], bVb[0] + kl);
                ldsm4(bfr[1], bVb[1] + kl);
                #pragma unroll
                for (int nt = 0; nt < 4; nt++)
                    mma16(oacc[nt], pa[kk][0], pa[kk][1], pa[kk][2], pa[kk][3],
                          bfr[nt >> 1][(nt & 1) * 2], bfr[nt >> 1][(nt & 1) * 2 + 1]);
            }
            const int row0 = R + g, row1 = R + 8 + g;
            const int cb = (h0 + ahh) * 32;
            #pragma unroll
            for (int nt = 0; nt < 4; nt++) {
                const int c = cb + nt * 8 + 2 * tg;
                if (row0 < 49)
                    *(__half2*)&s_o[row0 * HO + c] =
                        __floats2half2_rn(oacc[nt][0], oacc[nt][1]);
                if (row1 < 49)
                    *(__half2*)&s_o[row1 * HO + c] =
                        __floats2half2_rn(oacc[nt][2], oacc[nt][3]);
            }
        }
    } // head pairs
    __syncthreads();

    // ======= proj: out = O[64,256] @ Wp + b (prefetched smem staging) ======
    {
        float facc[2][8][4];
        #pragma unroll
        for (int mt = 0; mt < 2; mt++)
            #pragma unroll
            for (int j = 0; j < 8; j++) {
                facc[mt][j][0] = 0.f; facc[mt][j][1] = 0.f;
                facc[mt][j][2] = 0.f; facc[mt][j][3] = 0.f;
            }
        const int pn = tid >> 2, pc8 = tid & 3;
        uint4 pf[4];
        #pragma unroll
        for (int i = 0; i < 4; i++)
            pf[i] = *(const uint4*)&g_wph[(size_t)(pn + i * 64) * 256 + pc8 * 8];
        for (int kc = 0; kc < 8; kc++) {
            __syncthreads();
            #pragma unroll
            for (int i = 0; i < 4; i++)
                *(uint4*)&s_u[(pn + i * 64) * HWP + pc8 * 8] = pf[i];
            if (kc < 7) {
                #pragma unroll
                for (int i = 0; i < 4; i++)
                    pf[i] = *(const uint4*)&g_wph[(size_t)(pn + i * 64) * 256 +
                                                  (kc + 1) * 32 + pc8 * 8];
            }
            __syncthreads();
            #pragma unroll
            for (int kk = 0; kk < 2; kk++) {
                const uint32_t koff = (kc * 32 + kk * 16) * 2;
                const uint32_t kl = kk * 32;
                uint32_t a[2][4], bfr[4][4];
                ldsm4(a[0], aOb[0] + koff);
                ldsm4(a[1], aOb[1] + koff);
                ldsm4(bfr[0], bWP[0] + kl);
                ldsm4(bfr[1], bWP[1] + kl);
                ldsm4(bfr[2], bWP[2] + kl);
                ldsm4(bfr[3], bWP[3] + kl);
                #pragma unroll
                for (int nt = 0; nt < 8; nt++) {
                    uint32_t b0 = bfr[nt >> 1][(nt & 1) * 2];
                    uint32_t b1 = bfr[nt >> 1][(nt & 1) * 2 + 1];
                    mma16(facc[0][nt], a[0][0], a[0][1], a[0][2], a[0][3], b0, b1);
                    mma16(facc[1][nt], a[1][0], a[1][1], a[1][2], a[1][3], b0, b1);
                }
            }
        }
        // epilogue
        float* ob = out + (size_t)b * (NTOK * DIMC);
        #pragma unroll
        for (int mt = 0; mt < 2; mt++) {
            const int r0 = mi * 32 + mt * 16 + g, r1 = r0 + 8;
            #pragma unroll
            for (int nt = 0; nt < 8; nt++) {
                const int c = nb * 64 + nt * 8 + 2 * tg;
                if (r0 < NTOK) {
                    float2 v;
                    v.x = facc[mt][nt][0] + s_pb[c];
                    v.y = facc[mt][nt][1] + s_pb[c + 1];
                    *(float2*)(ob + r0 * DIMC + c) = v;
                }
                if (r1 < NTOK) {
                    float2 v;
                    v.x = facc[mt][nt][2] + s_pb[c];
                    v.y = facc[mt][nt][3] + s_pb[c + 1];
                    *(float2*)(ob + r1 * DIMC + c) = v;
                }
            }
        }
    }
}

extern "C" void kernel_launch(void* const* d_in, const int* in_sizes, int n_in,
                              void* d_out, int out_size) {
    (void)in_sizes; (void)n_in; (void)out_size;
    const float* x      = (const float*)d_in[0];
    const float* qkv_w  = (const float*)d_in[1];
    const float* proj_w = (const float*)d_in[2];
    const float* proj_b = (const float*)d_in[3];
    const float* bt     = (const float*)d_in[4];
    const int*   ri     = (const int*)d_in[5];
    float* out = (float*)d_out;

    prep_kernel<<<226, 256>>>(qkv_w, proj_w, bt, ri);
    cudaFuncSetAttribute(win_attn_kernel,
                         cudaFuncAttributeMaxDynamicSharedMemorySize, SMEM_BYTES);
    win_attn_kernel<<<4096, 256, SMEM_BYTES>>>(x, proj_b, out);
}

// round 12
// speedup vs baseline: 4.0598x; 1.1649x over previous
#include <cuda_runtime.h>
#include <cuda_fp16.h>
#include <cstdint>

// ---------------------------------------------------------------------------
// WindowAttention fused (1 CTA = 1 window), FP16 mma m16n8k16 (f32 acc).
// R12: BOTH weight GEMMs stream B-fragments directly from L2 in consumption
// order (g_w1f + g_wpf fragment tables); proj smem staging fully removed.
// ---------------------------------------------------------------------------

constexpr int NTOK = 49;
constexpr int DIMC = 256;

// strides in halves
constexpr int HX  = 264;
constexpr int HQ  = 72;
constexpr int HK  = 72;
constexpr int HV  = 72;   // v^T [dim][token]
constexpr int HO  = 264;

constexpr int OFF_X = 0;                 // 49*264 = 12936
constexpr int OFF_Q = 12944;
constexpr int OFF_K = OFF_Q + 64 * HQ;   // 17552
constexpr int OFF_V = OFF_K + 64 * HK;   // 22160
constexpr int OFF_O = OFF_V + 64 * HV;   // 26768
constexpr int HALVES = 39712;            // O ends 39704, align 16B
constexpr int SMEM_BYTES = HALVES * 2 + 256 * 4;   // + proj_b -> 80448 B

// W1 fragments: block (hp,kc,kk,nb,nf) of 32 uint4; lane's uint4 = 4 frag regs
__device__ uint4 g_w1f[4 * 8 * 2 * 4 * 3 * 32];   // 384 KB
// Wp fragments: block (kc,kk,nb,nf) of 32 uint4
__device__ uint4 g_wpf[8 * 2 * 4 * 4 * 32];        // 128 KB
__device__ float g_biasf[8 * 49 * 64];             // bias[h][row][col], 100 KB

__global__ void prep_kernel(const float* __restrict__ qkv_w,
                            const float* __restrict__ proj_w,
                            const float* __restrict__ bias_table,
                            const int*   __restrict__ rel_idx) {
    int t = blockIdx.x * blockDim.x + threadIdx.x;
    if (t < 24576) {
        // --- W1 fragment packing ---
        int lane = t & 31;
        int r2 = t >> 5;
        int nf = r2 % 3;  int r3 = r2 / 3;
        int nb = r3 & 3;  int r4 = r3 >> 2;
        int kk = r4 & 1;  int r5 = r4 >> 1;
        int kc = r5 & 7;  int hp = r5 >> 3;
        int h0 = 2 * hp;
        uint32_t wr[4];
        #pragma unroll
        for (int t4 = 0; t4 < 4; t4++) {
            int rowt = (t4 & 2) ? 8 : 0;
            int coft = (t4 & 1) ? 8 : 0;
            int r  = nb * 48 + nf * 16 + rowt + (lane >> 2);
            int gn = (r >> 6) * 256 + (h0 + ((r & 63) >> 5)) * 32 + (r & 31);
            int k  = kc * 32 + kk * 16 + coft + 2 * (lane & 3);
            __half2 hv = __floats2half2_rn(qkv_w[(size_t)k * 768 + gn],
                                           qkv_w[(size_t)(k + 1) * 768 + gn]);
            wr[t4] = *(uint32_t*)&hv;
        }
        g_w1f[t] = make_uint4(wr[0], wr[1], wr[2], wr[3]);
    } else if (t < 32768) {
        // --- Wp fragment packing: r2 = (kc*2+kk)*16 + nb*4 + nf ---
        int u = t - 24576;
        int lane = u & 31;
        int r2 = u >> 5;
        int nf = r2 & 3;  int r3 = r2 >> 2;
        int nb = r3 & 3;  int r4 = r3 >> 2;
        int kk = r4 & 1;  int kc = r4 >> 1;
        uint32_t wr[4];
        #pragma unroll
        for (int t4 = 0; t4 < 4; t4++) {
            int rowt = (t4 & 2) ? 8 : 0;
            int coft = (t4 & 1) ? 8 : 0;
            int gn = nb * 64 + nf * 16 + rowt + (lane >> 2);
            int k  = kc * 32 + kk * 16 + coft + 2 * (lane & 3);
            __half2 hv = __floats2half2_rn(proj_w[(size_t)k * 256 + gn],
                                           proj_w[(size_t)(k + 1) * 256 + gn]);
            wr[t4] = *(uint32_t*)&hv;
        }
        g_wpf[u] = make_uint4(wr[0], wr[1], wr[2], wr[3]);
    } else {
        // --- bias matrix ---
        int u = t - 32768;
        if (u < 25088) {
            int h = u / 3136, rem = u % 3136;
            int r = rem >> 6, c = rem & 63;
            g_biasf[u] = (c < 49)
                ? bias_table[rel_idx[r * 49 + c] * 8 + h]
                : -30000.0f;
        }
    }
}

__device__ __forceinline__ void mma16(float c[4],
                                      uint32_t a0, uint32_t a1, uint32_t a2, uint32_t a3,
                                      uint32_t b0, uint32_t b1) {
    asm volatile(
        "mma.sync.aligned.m16n8k16.row.col.f32.f16.f16.f32 "
        "{%0,%1,%2,%3}, {%4,%5,%6,%7}, {%8,%9}, {%0,%1,%2,%3};"
        : "+f"(c[0]), "+f"(c[1]), "+f"(c[2]), "+f"(c[3])
        : "r"(a0), "r"(a1), "r"(a2), "r"(a3), "r"(b0), "r"(b1));
}
__device__ __forceinline__ void ldsm4(uint32_t r[4], uint32_t a) {
    asm volatile("ldmatrix.sync.aligned.m8n8.x4.shared.b16 {%0,%1,%2,%3}, [%4];"
        : "=r"(r[0]), "=r"(r[1]), "=r"(r[2]), "=r"(r[3]) : "r"(a));
}
__device__ __forceinline__ uint32_t packh2(float x, float y) {
    __half2 h = __floats2half2_rn(x, y);
    return *(uint32_t*)&h;
}

__global__ void __launch_bounds__(256, 2)
win_attn_kernel(const float* __restrict__ x,
                const float* __restrict__ proj_b,
                float*       __restrict__ out) {
    extern __shared__ __half sh[];
    __half* s_x = sh + OFF_X;
    __half* s_q = sh + OFF_Q;
    __half* s_k = sh + OFF_K;
    __half* s_v = sh + OFF_V;
    __half* s_o = sh + OFF_O;
    float* s_pb = (float*)((char*)sh + HALVES * 2);
    const uint32_t sb = (uint32_t)__cvta_generic_to_shared(sh);

    const int tid  = threadIdx.x;
    const int w    = tid >> 5;
    const int lane = tid & 31;
    const int g    = lane >> 2;
    const int tg   = lane & 3;
    const int b    = blockIdx.x;

    const int mi = w & 1;          // GEMM1/proj 32-row block
    const int nb = w >> 1;         // GEMM1/proj N block
    const int ahh = w >> 2;        // attention: head within pair
    const int R   = (w & 3) * 16;  // attention: row base

    // ldmatrix lane decomposition
    const int arow_in = (lane & 7) | (((lane >> 3) & 1) << 3);
    const int acol8   = (lane >> 4) << 3;
    const int brow_in = (lane & 7) | (((lane >> 4) & 1) << 3);
    const int bcol8   = ((lane >> 3) & 1) << 3;

    // ---- init: stage x (f32->half), proj_b ----
    {
        const float4* x4 = (const float4*)(x + (size_t)b * (NTOK * DIMC));
        #pragma unroll
        for (int i = 0; i < 13; i++) {
            int idx = tid + i * 256;
            if (idx < 3136) {
                int r = idx >> 6, c4 = idx & 63;
                float4 v = x4[idx];
                __half2* dst = (__half2*)&s_x[r * HX + c4 * 4];
                dst[0] = __floats2half2_rn(v.x, v.y);
                dst[1] = __floats2half2_rn(v.z, v.w);
            }
        }
        if (tid < 256) s_pb[tid] = proj_b[tid];
    }
    __syncthreads();

    const float scale = 0.17677669529663687f;  // 1/sqrt(32)

    // precomputed byte addresses
    uint32_t aXb[2];
    #pragma unroll
    for (int mt = 0; mt < 2; mt++) {
        int r = mi * 32 + mt * 16 + arow_in;
        int rc = (r < 49) ? r : 48;
        aXb[mt] = sb + 2 * (OFF_X + rc * HX + acol8);
    }
    const uint32_t aQb = sb + 2 * (OFF_Q + (R + arow_in) * HQ + ahh * 32 + acol8);
    uint32_t bKb[4];
    #pragma unroll
    for (int nf = 0; nf < 4; nf++)
        bKb[nf] = sb + 2 * (OFF_K + (nf * 16 + brow_in) * HK + ahh * 32 + bcol8);
    uint32_t bVb[2];
    #pragma unroll
    for (int nf = 0; nf < 2; nf++)
        bVb[nf] = sb + 2 * (OFF_V + (ahh * 32 + nf * 16 + brow_in) * HV + bcol8);
    uint32_t aOb[2];
    #pragma unroll
    for (int mt = 0; mt < 2; mt++) {
        int r = mi * 32 + mt * 16 + arow_in;
        int rc = (r < 49) ? r : 48;
        aOb[mt] = sb + 2 * (OFF_O + rc * HO + acol8);
    }

    for (int hp = 0; hp < 4; hp++) {
        const int h0 = 2 * hp;

        // ======= GEMM1: qkv_pair[64,192] = x @ W1, B streamed from L2 ======
        float acc1[2][6][4];
        #pragma unroll
        for (int mt = 0; mt < 2; mt++)
            #pragma unroll
            for (int nt = 0; nt < 6; nt++) {
                acc1[mt][nt][0] = 0.f; acc1[mt][nt][1] = 0.f;
                acc1[mt][nt][2] = 0.f; acc1[mt][nt][3] = 0.f;
            }
        {
            const uint4* wp = g_w1f + (size_t)hp * (16 * 384) + nb * 96 + lane;
            uint4 bv0 = wp[0], bv1 = wp[32], bv2 = wp[64];
            #pragma unroll
            for (int i = 0; i < 16; i++) {
                uint4 nx0, nx1, nx2;
                if (i < 15) {
                    const uint4* np = wp + (i + 1) * 384;
                    nx0 = np[0]; nx1 = np[32]; nx2 = np[64];
                }
                uint32_t a[2][4];
                ldsm4(a[0], aXb[0] + i * 32);
                ldsm4(a[1], aXb[1] + i * 32);
                mma16(acc1[0][0], a[0][0], a[0][1], a[0][2], a[0][3], bv0.x, bv0.y);
                mma16(acc1[1][0], a[1][0], a[1][1], a[1][2], a[1][3], bv0.x, bv0.y);
                mma16(acc1[0][1], a[0][0], a[0][1], a[0][2], a[0][3], bv0.z, bv0.w);
                mma16(acc1[1][1], a[1][0], a[1][1], a[1][2], a[1][3], bv0.z, bv0.w);
                mma16(acc1[0][2], a[0][0], a[0][1], a[0][2], a[0][3], bv1.x, bv1.y);
                mma16(acc1[1][2], a[1][0], a[1][1], a[1][2], a[1][3], bv1.x, bv1.y);
                mma16(acc1[0][3], a[0][0], a[0][1], a[0][2], a[0][3], bv1.z, bv1.w);
                mma16(acc1[1][3], a[1][0], a[1][1], a[1][2], a[1][3], bv1.z, bv1.w);
                mma16(acc1[0][4], a[0][0], a[0][1], a[0][2], a[0][3], bv2.x, bv2.y);
                mma16(acc1[1][4], a[1][0], a[1][1], a[1][2], a[1][3], bv2.x, bv2.y);
                mma16(acc1[0][5], a[0][0], a[0][1], a[0][2], a[0][3], bv2.z, bv2.w);
                mma16(acc1[1][5], a[1][0], a[1][1], a[1][2], a[1][3], bv2.z, bv2.w);
                if (i < 15) { bv0 = nx0; bv1 = nx1; bv2 = nx2; }
            }
        }
        // barrier: prior pair's scores/PV reads of s_q/k/v must be done
        __syncthreads();
        // scatter q (scaled) / k / v^T
        #pragma unroll
        for (int mt = 0; mt < 2; mt++) {
            const int r0 = mi * 32 + mt * 16 + g, r1 = r0 + 8;
            #pragma unroll
            for (int nt = 0; nt < 6; nt++) {
                const int colb = nb * 48 + nt * 8;
                const int s = colb >> 6;
                const int cc = (colb & 63) + 2 * tg;
                if (s == 0) {
                    *(__half2*)&s_q[r0 * HQ + cc] =
                        __floats2half2_rn(acc1[mt][nt][0] * scale, acc1[mt][nt][1] * scale);
                    *(__half2*)&s_q[r1 * HQ + cc] =
                        __floats2half2_rn(acc1[mt][nt][2] * scale, acc1[mt][nt][3] * scale);
                } else if (s == 1) {
                    *(__half2*)&s_k[r0 * HK + cc] =
                        __floats2half2_rn(acc1[mt][nt][0], acc1[mt][nt][1]);
                    *(__half2*)&s_k[r1 * HK + cc] =
                        __floats2half2_rn(acc1[mt][nt][2], acc1[mt][nt][3]);
                } else {
                    s_v[cc * HV + r0]       = __float2half_rn(acc1[mt][nt][0]);
                    s_v[(cc + 1) * HV + r0] = __float2half_rn(acc1[mt][nt][1]);
                    s_v[cc * HV + r1]       = __float2half_rn(acc1[mt][nt][2]);
                    s_v[(cc + 1) * HV + r1] = __float2half_rn(acc1[mt][nt][3]);
                }
            }
        }
        __syncthreads();

        // ======= scores: warp = 16 rows x 64 cols of one head ==============
        float sacc[8][4];
        #pragma unroll
        for (int nt = 0; nt < 8; nt++) {
            sacc[nt][0] = 0.f; sacc[nt][1] = 0.f;
            sacc[nt][2] = 0.f; sacc[nt][3] = 0.f;
        }
        #pragma unroll
        for (int kk = 0; kk < 2; kk++) {
            const uint32_t kl = kk * 32;
            uint32_t a[4], bfr[4][4];
            ldsm4(a, aQb + kl);
            ldsm4(bfr[0], bKb[0] + kl);
            ldsm4(bfr[1], bKb[1] + kl);
            ldsm4(bfr[2], bKb[2] + kl);
            ldsm4(bfr[3], bKb[3] + kl);
            #pragma unroll
            for (int nt = 0; nt < 8; nt++)
                mma16(sacc[nt], a[0], a[1], a[2], a[3],
                      bfr[nt >> 1][(nt & 1) * 2], bfr[nt >> 1][(nt & 1) * 2 + 1]);
        }

        // ======= softmax in registers; bias from L2-hot precomputed matrix =
        uint32_t pa[4][4];
        {
            const int head = h0 + ahh;
            const int row0 = R + g, row1 = R + 8 + g;
            const int rs0 = (row0 < 49) ? row0 : 48;
            const int rs1 = (row1 < 49) ? row1 : 48;
            const float* b0p = g_biasf + (head * 49 + rs0) * 64;
            const float* b1p = g_biasf + (head * 49 + rs1) * 64;
            float mx0 = -1e30f, mx1 = -1e30f;
            #pragma unroll
            for (int nt = 0; nt < 8; nt++) {
                const int c0 = nt * 8 + 2 * tg;
                float2 bA = *(const float2*)(b0p + c0);
                float2 bB = *(const float2*)(b1p + c0);
                float v;
                v = sacc[nt][0] + bA.x; sacc[nt][0] = v; mx0 = fmaxf(mx0, v);
                v = sacc[nt][1] + bA.y; sacc[nt][1] = v; mx0 = fmaxf(mx0, v);
                v = sacc[nt][2] + bB.x; sacc[nt][2] = v; mx1 = fmaxf(mx1, v);
                v = sacc[nt][3] + bB.y; sacc[nt][3] = v; mx1 = fmaxf(mx1, v);
            }
            mx0 = fmaxf(mx0, __shfl_xor_sync(0xffffffffu, mx0, 1, 4));
            mx0 = fmaxf(mx0, __shfl_xor_sync(0xffffffffu, mx0, 2, 4));
            mx1 = fmaxf(mx1, __shfl_xor_sync(0xffffffffu, mx1, 1, 4));
            mx1 = fmaxf(mx1, __shfl_xor_sync(0xffffffffu, mx1, 2, 4));
            float sum0 = 0.f, sum1 = 0.f;
            #pragma unroll
            for (int nt = 0; nt < 8; nt++) {
                float e;
                e = __expf(sacc[nt][0] - mx0); sacc[nt][0] = e; sum0 += e;
                e = __expf(sacc[nt][1] - mx0); sacc[nt][1] = e; sum0 += e;
                e = __expf(sacc[nt][2] - mx1); sacc[nt][2] = e; sum1 += e;
                e = __expf(sacc[nt][3] - mx1); sacc[nt][3] = e; sum1 += e;
            }
            sum0 += __shfl_xor_sync(0xffffffffu, sum0, 1, 4);
            sum0 += __shfl_xor_sync(0xffffffffu, sum0, 2, 4);
            sum1 += __shfl_xor_sync(0xffffffffu, sum1, 1, 4);
            sum1 += __shfl_xor_sync(0xffffffffu, sum1, 2, 4);
            const float ri0 = 1.0f / sum0, ri1 = 1.0f / sum1;
            #pragma unroll
            for (int kk = 0; kk < 4; kk++) {
                pa[kk][0] = packh2(sacc[2 * kk][0] * ri0, sacc[2 * kk][1] * ri0);
                pa[kk][1] = packh2(sacc[2 * kk][2] * ri1, sacc[2 * kk][3] * ri1);
                pa[kk][2] = packh2(sacc[2 * kk + 1][0] * ri0, sacc[2 * kk + 1][1] * ri0);
                pa[kk][3] = packh2(sacc[2 * kk + 1][2] * ri1, sacc[2 * kk + 1][3] * ri1);
            }
        }

        // ======= O = P @ v^T (P in regs) ; store half to s_o ===============
        {
            float oacc[4][4];
            #pragma unroll
            for (int nt = 0; nt < 4; nt++) {
                oacc[nt][0] = 0.f; oacc[nt][1] = 0.f;
                oacc[nt][2] = 0.f; oacc[nt][3] = 0.f;
            }
            #pragma unroll
            for (int kk = 0; kk < 4; kk++) {
                const uint32_t kl = kk * 32;
                uint32_t bfr[2][4];
                ldsm4(bfr[0], bVb[0] + kl);
                ldsm4(bfr[1], bVb[1] + kl);
                #pragma unroll
                for (int nt = 0; nt < 4; nt++)
                    mma16(oacc[nt], pa[kk][0], pa[kk][1], pa[kk][2], pa[kk][3],
                          bfr[nt >> 1][(nt & 1) * 2], bfr[nt >> 1][(nt & 1) * 2 + 1]);
            }
            const int row0 = R + g, row1 = R + 8 + g;
            const int cb = (h0 + ahh) * 32;
            #pragma unroll
            for (int nt = 0; nt < 4; nt++) {
                const int c = cb + nt * 8 + 2 * tg;
                if (row0 < 49)
                    *(__half2*)&s_o[row0 * HO + c] =
                        __floats2half2_rn(oacc[nt][0], oacc[nt][1]);
                if (row1 < 49)
                    *(__half2*)&s_o[row1 * HO + c] =
                        __floats2half2_rn(oacc[nt][2], oacc[nt][3]);
            }
        }
    } // head pairs
    __syncthreads();

    // ======= proj: out = O[64,256] @ Wp + b, B streamed from L2 ============
    {
        float facc[2][8][4];
        #pragma unroll
        for (int mt = 0; mt < 2; mt++)
            #pragma unroll
            for (int j = 0; j < 8; j++) {
                facc[mt][j][0] = 0.f; facc[mt][j][1] = 0.f;
                facc[mt][j][2] = 0.f; facc[mt][j][3] = 0.f;
            }
        const uint4* wp = g_wpf + nb * 128 + lane;
        #pragma unroll
        for (int i = 0; i < 16; i++) {
            const uint4* bp = wp + i * 512;
            uint4 bv0 = bp[0], bv1 = bp[32], bv2 = bp[64], bv3 = bp[96];
            uint32_t a[2][4];
            ldsm4(a[0], aOb[0] + i * 32);
            ldsm4(a[1], aOb[1] + i * 32);
            mma16(facc[0][0], a[0][0], a[0][1], a[0][2], a[0][3], bv0.x, bv0.y);
            mma16(facc[1][0], a[1][0], a[1][1], a[1][2], a[1][3], bv0.x, bv0.y);
            mma16(facc[0][1], a[0][0], a[0][1], a[0][2], a[0][3], bv0.z, bv0.w);
            mma16(facc[1][1], a[1][0], a[1][1], a[1][2], a[1][3], bv0.z, bv0.w);
            mma16(facc[0][2], a[0][0], a[0][1], a[0][2], a[0][3], bv1.x, bv1.y);
            mma16(facc[1][2], a[1][0], a[1][1], a[1][2], a[1][3], bv1.x, bv1.y);
            mma16(facc[0][3], a[0][0], a[0][1], a[0][2], a[0][3], bv1.z, bv1.w);
            mma16(facc[1][3], a[1][0], a[1][1], a[1][2], a[1][3], bv1.z, bv1.w);
            mma16(facc[0][4], a[0][0], a[0][1], a[0][2], a[0][3], bv2.x, bv2.y);
            mma16(facc[1][4], a[1][0], a[1][1], a[1][2], a[1][3], bv2.x, bv2.y);
            mma16(facc[0][5], a[0][0], a[0][1], a[0][2], a[0][3], bv2.z, bv2.w);
            mma16(facc[1][5], a[1][0], a[1][1], a[1][2], a[1][3], bv2.z, bv2.w);
            mma16(facc[0][6], a[0][0], a[0][1], a[0][2], a[0][3], bv3.x, bv3.y);
            mma16(facc[1][6], a[1][0], a[1][1], a[1][2], a[1][3], bv3.x, bv3.y);
            mma16(facc[0][7], a[0][0], a[0][1], a[0][2], a[0][3], bv3.z, bv3.w);
            mma16(facc[1][7], a[1][0], a[1][1], a[1][2], a[1][3], bv3.z, bv3.w);
        }
        // epilogue
        float* ob = out + (size_t)b * (NTOK * DIMC);
        #pragma unroll
        for (int mt = 0; mt < 2; mt++) {
            const int r0 = mi * 32 + mt * 16 + g, r1 = r0 + 8;
            #pragma unroll
            for (int nt = 0; nt < 8; nt++) {
                const int c = nb * 64 + nt * 8 + 2 * tg;
                if (r0 < NTOK) {
                    float2 v;
                    v.x = facc[mt][nt][0] + s_pb[c];
                    v.y = facc[mt][nt][1] + s_pb[c + 1];
                    *(float2*)(ob + r0 * DIMC + c) = v;
                }
                if (r1 < NTOK) {
                    float2 v;
                    v.x = facc[mt][nt][2] + s_pb[c];
                    v.y = facc[mt][nt][3] + s_pb[c + 1];
                    *(float2*)(ob + r1 * DIMC + c) = v;
                }
            }
        }
    }
}

extern "C" void kernel_launch(void* const* d_in, const int* in_sizes, int n_in,
                              void* d_out, int out_size) {
    (void)in_sizes; (void)n_in; (void)out_size;
    const float* x      = (const float*)d_in[0];
    const float* qkv_w  = (const float*)d_in[1];
    const float* proj_w = (const float*)d_in[2];
    const float* proj_b = (const float*)d_in[3];
    const float* bt     = (const float*)d_in[4];
    const int*   ri     = (const int*)d_in[5];
    float* out = (float*)d_out;

    prep_kernel<<<226, 256>>>(qkv_w, proj_w, bt, ri);
    cudaFuncSetAttribute(win_attn_kernel,
                         cudaFuncAttributeMaxDynamicSharedMemorySize, SMEM_BYTES);
    win_attn_kernel<<<4096, 256, SMEM_BYTES>>>(x, proj_b, out);
}